// round 6
// baseline (speedup 1.0000x reference)
#include <cuda_runtime.h>
#include <cuda_bf16.h>

#define Bb 64
#define Tt 64
#define Hh 1024
#define Vv 32000
#define Ee 512
#define WHH (4 * Hh * Hh)

// ---------------- scratch (static device memory; no allocation) ----------------
__device__ float g_xbuf[Tt * Bb * Ee];
__device__ float g_h[8 * Bb * Hh];              // fp32 initial h staging
__device__ float g_c[4 * Bb * Hh];
__device__ float g_zpre[Tt * Bb * 4 * Hh];
__device__ __nv_bfloat16 g_Ahi[4096 * 1024];
__device__ __nv_bfloat16 g_Alo[4096 * 1024];
__device__ __nv_bfloat16 g_B1hi[4096 * 512];
__device__ __nv_bfloat16 g_B1lo[4096 * 512];
__device__ __nv_bfloat16 g_Bhi[(size_t)Vv * 1024];
__device__ __nv_bfloat16 g_Blo[(size_t)Vv * 1024];
__device__ __nv_bfloat16 g_hsp_hi[8 * Bb * Hh];
__device__ __nv_bfloat16 g_hsp_lo[8 * Bb * Hh];
__device__ __nv_bfloat16 g_Wsp_hi[3 * WHH];
__device__ __nv_bfloat16 g_Wsp_lo[3 * WHH];
__device__ __nv_bfloat16 g_Usp_hi[4 * WHH];
__device__ __nv_bfloat16 g_Usp_lo[4 * WHH];

struct CellArgs {
    const float* b[4];
};

// ---------------- cp.async / ldmatrix / mma helpers -----------------------------
__device__ __forceinline__ void cp16(void* smem_dst, const void* gsrc) {
    unsigned s = (unsigned)__cvta_generic_to_shared(smem_dst);
    asm volatile("cp.async.cg.shared.global [%0], [%1], 16;\n" :: "r"(s), "l"(gsrc));
}
__device__ __forceinline__ void cp_commit() {
    asm volatile("cp.async.commit_group;\n" ::: "memory");
}
__device__ __forceinline__ void cp_wait2() {
    asm volatile("cp.async.wait_group 2;\n" ::: "memory");
}

__device__ __forceinline__ void ldsm_x4(unsigned& r0, unsigned& r1, unsigned& r2,
                                        unsigned& r3, unsigned addr) {
    asm volatile("ldmatrix.sync.aligned.m8n8.x4.shared.b16 {%0,%1,%2,%3}, [%4];"
                 : "=r"(r0), "=r"(r1), "=r"(r2), "=r"(r3) : "r"(addr));
}
__device__ __forceinline__ void ldsm_x2(unsigned& r0, unsigned& r1, unsigned addr) {
    asm volatile("ldmatrix.sync.aligned.m8n8.x2.shared.b16 {%0,%1}, [%2];"
                 : "=r"(r0), "=r"(r1) : "r"(addr));
}

__device__ __forceinline__ void mma16816(float c[4],
                                         unsigned a0, unsigned a1, unsigned a2, unsigned a3,
                                         unsigned b0, unsigned b1) {
    asm volatile(
        "mma.sync.aligned.m16n8k16.row.col.f32.bf16.bf16.f32 "
        "{%0,%1,%2,%3}, {%4,%5,%6,%7}, {%8,%9}, {%0,%1,%2,%3};"
        : "+f"(c[0]), "+f"(c[1]), "+f"(c[2]), "+f"(c[3])
        : "r"(a0), "r"(a1), "r"(a2), "r"(a3), "r"(b0), "r"(b1));
}

// ---------------- embedding lookup ---------------------------------------------
__global__ __launch_bounds__(256) void embed_k(const int* __restrict__ tok,
                                               const float* __restrict__ emb) {
    int idx = blockIdx.x * 256 + threadIdx.x;
    int e  = idx & (Ee - 1);
    int bt = idx >> 9;
    int b  = bt & (Bb - 1);
    int t  = bt >> 6;
    g_xbuf[idx] = emb[(size_t)tok[b * Tt + t] * Ee + e];
}

// ---------------- fp32 -> (hi, lo) bf16 split ----------------------------------
__global__ __launch_bounds__(256) void split_k(const float* __restrict__ src,
                                               __nv_bfloat16* __restrict__ hi,
                                               __nv_bfloat16* __restrict__ lo, int n) {
    int i = blockIdx.x * 256 + threadIdx.x;
    if (i < n) {
        float x = src[i];
        __nv_bfloat16 h = __float2bfloat16(x);
        hi[i] = h;
        lo[i] = __float2bfloat16(x - __bfloat162float(h));
    }
}

// ---------------- split initial h states ---------------------------------------
__global__ __launch_bounds__(256) void hinit_split_k() {
    int i = blockIdx.x * 256 + threadIdx.x;
    int l = i >> 16;
    int r = i & 65535;
    size_t o = ((size_t)(l * 2)) * (Bb * Hh) + r;
    float x = g_h[o];
    __nv_bfloat16 h = __float2bfloat16(x);
    g_hsp_hi[o] = h;
    g_hsp_lo[o] = __float2bfloat16(x - __bfloat162float(h));
}

// ---------------- transpose + split: src[K][N] -> hi/lo [N][K] ------------------
__global__ __launch_bounds__(256) void tsplit_k(const float* __restrict__ src,
                                                __nv_bfloat16* __restrict__ hi,
                                                __nv_bfloat16* __restrict__ lo,
                                                int K, int N) {
    __shared__ float tile[32][33];
    int k0 = blockIdx.x * 32, n0 = blockIdx.y * 32;
    int tx = threadIdx.x & 31, ty = threadIdx.x >> 5;
#pragma unroll
    for (int j = 0; j < 32; j += 8)
        tile[ty + j][tx] = src[(size_t)(k0 + ty + j) * N + n0 + tx];
    __syncthreads();
#pragma unroll
    for (int j = 0; j < 32; j += 8) {
        float x = tile[tx][ty + j];
        __nv_bfloat16 h = __float2bfloat16(x);
        size_t o = (size_t)(n0 + ty + j) * K + k0 + tx;
        hi[o] = h;
        lo[o] = __float2bfloat16(x - __bfloat162float(h));
    }
}

// ---------------- split-bf16 tensor-core GEMM (zpre + FC) -----------------------
// 4-stage cp.async, ldmatrix, 1 sync/iter. Block 128x128, k-chunk 32.
// Dynamic smem: As 4 stages of [128][40] bf16, then Bs same. 81920 bytes.
#define FC_LD 40
#define FC_STAGE (128 * FC_LD)          // elems per stage
__global__ __launch_bounds__(256) void mma_gemm_k(
    const __nv_bfloat16* __restrict__ Ahi, const __nv_bfloat16* __restrict__ Alo,
    const __nv_bfloat16* __restrict__ Bhi, const __nv_bfloat16* __restrict__ Blo,
    const float* __restrict__ bias,
    float* __restrict__ out, int K, int N, int perm)
{
    extern __shared__ __nv_bfloat16 smem[];
    __nv_bfloat16* AsBase = smem;
    __nv_bfloat16* BsBase = smem + 4 * FC_STAGE;
    const unsigned sb = (unsigned)__cvta_generic_to_shared(smem);
    const unsigned sbB = sb + 4 * FC_STAGE * 2;

    const int tid  = threadIdx.x;
    const int row0 = blockIdx.x * 128;
    const int col0 = blockIdx.y * 128;
    const int wid  = tid >> 5, lane = tid & 31;
    const int wm   = wid >> 2;
    const int wn   = wid & 3;
    const int g    = lane >> 2, tg = lane & 3;

    const int kps  = K >> 5;
    const int nit  = 3 * kps;

    float acc[4][4][4];
#pragma unroll
    for (int im = 0; im < 4; im++)
#pragma unroll
        for (int in_ = 0; in_ < 4; in_++)
#pragma unroll
            for (int q = 0; q < 4; q++) acc[im][in_][q] = 0.f;

    // cp coords: A/B each 128 rows x 32 k; 512 chunks(16B); 2 per thread
    const int ca  = tid * 2;
    const int ar0 = ca >> 2,       ao0 = (ca & 3) * 8;
    const int ar1 = (ca + 1) >> 2, ao1 = ((ca + 1) & 3) * 8;

    // ldmatrix lane offsets
    const int la_row = lane & 15;
    const int la_k   = (lane >> 4) * 8;
    const int lb_row = lane & 7;
    const int lb_k   = ((lane >> 3) & 1) * 8;

    auto issue = [&](int it, int buf) {
        int s  = (it >= 2 * kps) ? 2 : (it >= kps ? 1 : 0);
        int k0 = (it - s * kps) * 32;
        const __nv_bfloat16* A = (s == 1) ? Alo : Ahi;
        const __nv_bfloat16* B = (s == 2) ? Blo : Bhi;
        __nv_bfloat16* As = AsBase + buf * FC_STAGE;
        __nv_bfloat16* Bs = BsBase + buf * FC_STAGE;
        cp16(As + ar0 * FC_LD + ao0, A + (size_t)(row0 + ar0) * K + k0 + ao0);
        cp16(As + ar1 * FC_LD + ao1, A + (size_t)(row0 + ar1) * K + k0 + ao1);
        cp16(Bs + ar0 * FC_LD + ao0, B + (size_t)(col0 + ar0) * K + k0 + ao0);
        cp16(Bs + ar1 * FC_LD + ao1, B + (size_t)(col0 + ar1) * K + k0 + ao1);
        cp_commit();
    };

    issue(0, 0); issue(1, 1); issue(2, 2);

#pragma unroll 1
    for (int it = 0; it < nit; it++) {
        cp_wait2();
        __syncthreads();
        if (it + 3 < nit) issue(it + 3, (it + 3) & 3);
        const int buf = it & 3;
        const unsigned abuf = sb  + buf * FC_STAGE * 2;
        const unsigned bbuf = sbB + buf * FC_STAGE * 2;

#pragma unroll
        for (int kk = 0; kk < 32; kk += 16) {
            unsigned a[4][4], b[4][2];
#pragma unroll
            for (int im = 0; im < 4; im++) {
                unsigned ad = abuf +
                    ((wm * 64 + im * 16 + la_row) * FC_LD + kk + la_k) * 2;
                ldsm_x4(a[im][0], a[im][1], a[im][2], a[im][3], ad);
            }
#pragma unroll
            for (int in_ = 0; in_ < 4; in_++) {
                unsigned bd = bbuf +
                    ((wn * 32 + in_ * 8 + lb_row) * FC_LD + kk + lb_k) * 2;
                ldsm_x2(b[in_][0], b[in_][1], bd);
            }
#pragma unroll
            for (int im = 0; im < 4; im++)
#pragma unroll
                for (int in_ = 0; in_ < 4; in_++)
                    mma16816(acc[im][in_],
                             a[im][0], a[im][1], a[im][2], a[im][3],
                             b[in_][0], b[in_][1]);
        }
    }

#pragma unroll
    for (int im = 0; im < 4; im++) {
#pragma unroll
        for (int in_ = 0; in_ < 4; in_++) {
            int rr = row0 + wm * 64 + im * 16 + g;
            int cn = col0 + wn * 32 + in_ * 8 + tg * 2;
            float b0v = bias ? bias[cn] : 0.f;
            float b1v = bias ? bias[cn + 1] : 0.f;
#pragma unroll
            for (int half = 0; half < 2; half++) {
                int r = rr + half * 8;
                size_t orow;
                if (perm) {
                    int t = r >> 6, b = r & 63;
                    orow = (size_t)(b * Tt + t);
                } else {
                    orow = (size_t)r;
                }
                float2 v;
                v.x = acc[im][in_][half * 2 + 0] + b0v;
                v.y = acc[im][in_][half * 2 + 1] + b1v;
                *(float2*)(out + orow * N + cn) = v;
            }
        }
    }
}

// ---------------- wavefront LSTM cell on tensor cores ---------------------------
// 4-stage cp.async, ldmatrix, k-chunk 64, 1 sync/iter.
// Dynamic smem: As 4x[64][72] bf16, Bs same (73728 B); Zs aliases after drain.
#define WV_LD 72
#define WV_STAGE (64 * WV_LD)
__global__ __launch_bounds__(128) void lstm_wave_mma_k(CellArgs args, int s) {
    extern __shared__ __nv_bfloat16 smem[];
    __nv_bfloat16* AsBase = smem;
    __nv_bfloat16* BsBase = smem + 4 * WV_STAGE;
    float* Zs = (float*)smem;            // [64][68], used after mainloop
    const unsigned sb  = (unsigned)__cvta_generic_to_shared(smem);
    const unsigned sbB = sb + 4 * WV_STAGE * 2;

    const int lmin = (s > 63) ? (s - 63) : 0;
    const int l    = lmin + blockIdx.y;
    const int t    = s - l;
    const size_t SH = (size_t)Bb * Hh;
    const int pin  = t & 1, pout = (t + 1) & 1;
    const int j0   = blockIdx.x * 16;

    const __nv_bfloat16* h_hi = g_hsp_hi + (size_t)(l * 2 + pin) * SH;
    const __nv_bfloat16* h_lo = g_hsp_lo + (size_t)(l * 2 + pin) * SH;
    const __nv_bfloat16* Uhi  = g_Usp_hi + (size_t)l * WHH;
    const __nv_bfloat16* Ulo  = g_Usp_lo + (size_t)l * WHH;

    const __nv_bfloat16* Aseg[6];
    const __nv_bfloat16* Bseg[6];
    int nseg;
    if (l == 0) {
        Aseg[0] = h_hi; Bseg[0] = Uhi;
        Aseg[1] = h_lo; Bseg[1] = Uhi;
        Aseg[2] = h_hi; Bseg[2] = Ulo;
        nseg = 3;
    } else {
        const __nv_bfloat16* x_hi = g_hsp_hi + (size_t)((l - 1) * 2 + pout) * SH;
        const __nv_bfloat16* x_lo = g_hsp_lo + (size_t)((l - 1) * 2 + pout) * SH;
        const __nv_bfloat16* Whi  = g_Wsp_hi + (size_t)(l - 1) * WHH;
        const __nv_bfloat16* Wlo  = g_Wsp_lo + (size_t)(l - 1) * WHH;
        Aseg[0] = x_hi; Bseg[0] = Whi;
        Aseg[1] = x_lo; Bseg[1] = Whi;
        Aseg[2] = x_hi; Bseg[2] = Wlo;
        Aseg[3] = h_hi; Bseg[3] = Uhi;
        Aseg[4] = h_lo; Bseg[4] = Uhi;
        Aseg[5] = h_hi; Bseg[5] = Ulo;
        nseg = 6;
    }
    const int nit = nseg * 16;         // 16 chunks of 64 per K=1024 segment

    const int tid  = threadIdx.x;
    const int wn   = tid >> 5;
    const int lane = tid & 31;
    const int g    = lane >> 2, tg = lane & 3;

    // cp coords: A/B 64 rows x 64 k; 2 threads/row, 4x16B each
    const int arow = tid >> 1;
    const int acol = (tid & 1) * 32;
    const int bgrow = (arow >> 4) * Hh + j0 + (arow & 15);

    const int la_row = lane & 15;
    const int la_k   = (lane >> 4) * 8;
    const int lb_row = lane & 7;
    const int lb_k   = ((lane >> 3) & 1) * 8;

    float acc[4][2][4];
#pragma unroll
    for (int im = 0; im < 4; im++)
#pragma unroll
        for (int in_ = 0; in_ < 2; in_++)
#pragma unroll
            for (int q = 0; q < 4; q++) acc[im][in_][q] = 0.f;

    auto issue = [&](int it, int buf) {
        int seg = it >> 4;
        int k0  = (it & 15) * 64;
        const __nv_bfloat16* A  = Aseg[seg];
        const __nv_bfloat16* Bp = Bseg[seg];
        __nv_bfloat16* As = AsBase + buf * WV_STAGE;
        __nv_bfloat16* Bs = BsBase + buf * WV_STAGE;
#pragma unroll
        for (int q = 0; q < 4; q++) {
            cp16(As + arow * WV_LD + acol + q * 8,
                 A + (size_t)arow * Hh + k0 + acol + q * 8);
            cp16(Bs + arow * WV_LD + acol + q * 8,
                 Bp + (size_t)bgrow * Hh + k0 + acol + q * 8);
        }
        cp_commit();
    };

    issue(0, 0); issue(1, 1); issue(2, 2);

#pragma unroll 1
    for (int it = 0; it < nit; it++) {
        cp_wait2();
        __syncthreads();
        if (it + 3 < nit) issue(it + 3, (it + 3) & 3);
        const int buf = it & 3;
        const unsigned abuf = sb  + buf * WV_STAGE * 2;
        const unsigned bbuf = sbB + buf * WV_STAGE * 2;

#pragma unroll
        for (int kk = 0; kk < 64; kk += 16) {
            unsigned a[4][4], b[2][2];
#pragma unroll
            for (int im = 0; im < 4; im++) {
                unsigned ad = abuf + ((im * 16 + la_row) * WV_LD + kk + la_k) * 2;
                ldsm_x4(a[im][0], a[im][1], a[im][2], a[im][3], ad);
            }
#pragma unroll
            for (int in_ = 0; in_ < 2; in_++) {
                unsigned bd = bbuf +
                    ((wn * 16 + in_ * 8 + lb_row) * WV_LD + kk + lb_k) * 2;
                ldsm_x2(b[in_][0], b[in_][1], bd);
            }
#pragma unroll
            for (int im = 0; im < 4; im++)
#pragma unroll
                for (int in_ = 0; in_ < 2; in_++)
                    mma16816(acc[im][in_],
                             a[im][0], a[im][1], a[im][2], a[im][3],
                             b[in_][0], b[in_][1]);
        }
    }

    __syncthreads();     // drain: all warps done with pipeline buffers

    // scatter z fragments to smem for gate assembly
#pragma unroll
    for (int im = 0; im < 4; im++)
#pragma unroll
        for (int in_ = 0; in_ < 2; in_++)
#pragma unroll
            for (int q = 0; q < 4; q++) {
                int r = im * 16 + g + ((q >> 1) << 3);
                int n = wn * 16 + in_ * 8 + tg * 2 + (q & 1);
                Zs[r * 68 + n] = acc[im][in_][q];
            }
    __syncthreads();

    // gate epilogue: 64 rows x 16 units, 8 per thread
    const float* bias = args.b[l];
    float* c = g_c + (size_t)l * SH;
    __nv_bfloat16* ho_hi = g_hsp_hi + (size_t)(l * 2 + pout) * SH;
    __nv_bfloat16* ho_lo = g_hsp_lo + (size_t)(l * 2 + pout) * SH;
    const float* zp = (l == 0) ? (g_zpre + (size_t)t * Bb * 4 * Hh) : nullptr;

#pragma unroll
    for (int q = 0; q < 8; q++) {
        int e  = tid + 128 * q;
        int r  = e >> 4;
        int uu = e & 15;
        int j  = j0 + uu;
        float zi = Zs[r * 68 + uu]      + bias[j];
        float zf = Zs[r * 68 + 16 + uu] + bias[Hh + j];
        float zg = Zs[r * 68 + 32 + uu] + bias[2 * Hh + j];
        float zo = Zs[r * 68 + 48 + uu] + bias[3 * Hh + j];
        if (zp) {
            const float* z = zp + (size_t)r * (4 * Hh);
            zi += z[j]; zf += z[Hh + j]; zg += z[2 * Hh + j]; zo += z[3 * Hh + j];
        }
        float si = 1.f / (1.f + __expf(-zi));
        float sf = 1.f / (1.f + __expf(-zf));
        float so = 1.f / (1.f + __expf(-zo));
        float tg_ = tanhf(zg);
        float cn = sf * c[r * Hh + j] + si * tg_;
        float hn = so * tanhf(cn);
        c[r * Hh + j] = cn;
        __nv_bfloat16 hh = __float2bfloat16(hn);
        float lo = hn - __bfloat162float(hh);
        ho_hi[r * Hh + j] = hh;
        ho_lo[r * Hh + j] = __float2bfloat16(lo);
        if (l == 3) {
            size_t o = ((size_t)t * Bb + r) * Hh + j;
            g_Ahi[o] = hh;
            g_Alo[o] = __float2bfloat16(lo);
        }
    }
}

// ---------------- online softmax (2 reads + 1 write) ----------------------------
__global__ __launch_bounds__(256) void softmax_k(float* __restrict__ out) {
    __shared__ float mred[256], sred[256];
    float* p = out + (size_t)blockIdx.x * Vv;
    int tid = threadIdx.x;

    float m = -3.4e38f, sum = 0.f;
    for (int i = tid; i < Vv; i += 256) {
        float x = p[i];
        float mn = fmaxf(m, x);
        sum = sum * __expf(m - mn) + __expf(x - mn);
        m = mn;
    }
    mred[tid] = m; sred[tid] = sum; __syncthreads();
    for (int st = 128; st > 0; st >>= 1) {
        if (tid < st) {
            float m2 = mred[tid + st], s2 = sred[tid + st];
            float mn = fmaxf(mred[tid], m2);
            sred[tid] = sred[tid] * __expf(mred[tid] - mn) + s2 * __expf(m2 - mn);
            mred[tid] = mn;
        }
        __syncthreads();
    }
    float M = mred[0];
    float inv = 1.f / sred[0];
    for (int i = tid; i < Vv; i += 256) p[i] = __expf(p[i] - M) * inv;
}

// ---------------- launch ------------------------------------------------------
extern "C" void kernel_launch(void* const* d_in, const int* in_sizes, int n_in,
                              void* d_out, int out_size) {
    (void)in_sizes; (void)n_in; (void)out_size;
    const int*   tok = (const int*)d_in[0];
    const float* emb = (const float*)d_in[9];
    const float* W[4]; const float* U[4];
    CellArgs args;
    for (int l = 0; l < 4; l++) {
        W[l] = (const float*)d_in[10 + 3 * l];
        U[l] = (const float*)d_in[11 + 3 * l];
        args.b[l] = (const float*)d_in[12 + 3 * l];
    }
    const float* Wfc = (const float*)d_in[22];
    const float* bfc = (const float*)d_in[23];
    float* out = (float*)d_out;

    float *xbuf, *hbuf, *cbuf, *zpre;
    __nv_bfloat16 *Ahi, *Alo, *B1hi, *B1lo, *Bhi, *Blo, *Wsph, *Wspl, *Usph, *Uspl;
    cudaGetSymbolAddress((void**)&xbuf, g_xbuf);
    cudaGetSymbolAddress((void**)&hbuf, g_h);
    cudaGetSymbolAddress((void**)&cbuf, g_c);
    cudaGetSymbolAddress((void**)&zpre, g_zpre);
    cudaGetSymbolAddress((void**)&Ahi,  g_Ahi);
    cudaGetSymbolAddress((void**)&Alo,  g_Alo);
    cudaGetSymbolAddress((void**)&B1hi, g_B1hi);
    cudaGetSymbolAddress((void**)&B1lo, g_B1lo);
    cudaGetSymbolAddress((void**)&Bhi,  g_Bhi);
    cudaGetSymbolAddress((void**)&Blo,  g_Blo);
    cudaGetSymbolAddress((void**)&Wsph, g_Wsp_hi);
    cudaGetSymbolAddress((void**)&Wspl, g_Wsp_lo);
    cudaGetSymbolAddress((void**)&Usph, g_Usp_hi);
    cudaGetSymbolAddress((void**)&Uspl, g_Usp_lo);

    const int fcSmem = 4 * 2 * FC_STAGE * 2;     // 81920 bytes
    const int wvSmem = 4 * 2 * WV_STAGE * 2;     // 73728 bytes
    cudaFuncSetAttribute(mma_gemm_k,
                         cudaFuncAttributeMaxDynamicSharedMemorySize, fcSmem);
    cudaFuncSetAttribute(lstm_wave_mma_k,
                         cudaFuncAttributeMaxDynamicSharedMemorySize, wvSmem);

    const size_t SH = (size_t)Bb * Hh;

    for (int l = 0; l < 4; l++) {
        cudaMemcpyAsync(hbuf + (size_t)(l * 2) * SH, d_in[1 + 2 * l],
                        SH * sizeof(float), cudaMemcpyDeviceToDevice, 0);
        cudaMemcpyAsync(cbuf + (size_t)l * SH, d_in[2 + 2 * l],
                        SH * sizeof(float), cudaMemcpyDeviceToDevice, 0);
    }

    embed_k<<<(Tt * Bb * Ee) / 256, 256>>>(tok, emb);
    hinit_split_k<<<(4 * Bb * Hh) / 256, 256>>>();

    // zpre = x @ W1 on tensor cores
    split_k<<<(4096 * 512) / 256, 256>>>(xbuf, Ahi, Alo, 4096 * 512);
    tsplit_k<<<dim3(Ee / 32, (4 * Hh) / 32), 256>>>(W[0], B1hi, B1lo, Ee, 4 * Hh);
    mma_gemm_k<<<dim3(32, (4 * Hh) / 128), 256, fcSmem>>>(
        Ahi, Alo, B1hi, B1lo, nullptr, zpre, Ee, 4 * Hh, 0);

    // transpose+split recurrent weights
    for (int l = 1; l < 4; l++)
        tsplit_k<<<dim3(Hh / 32, (4 * Hh) / 32), 256>>>(
            W[l], Wsph + (size_t)(l - 1) * WHH, Wspl + (size_t)(l - 1) * WHH,
            Hh, 4 * Hh);
    for (int l = 0; l < 4; l++)
        tsplit_k<<<dim3(Hh / 32, (4 * Hh) / 32), 256>>>(
            U[l], Usph + (size_t)l * WHH, Uspl + (size_t)l * WHH, Hh, 4 * Hh);

    // wavefront over diagonals
    for (int s = 0; s <= Tt + 3 - 1; s++) {
        int lmin = (s > Tt - 1) ? (s - (Tt - 1)) : 0;
        int lmax = (s < 3) ? s : 3;
        int ny   = lmax - lmin + 1;
        lstm_wave_mma_k<<<dim3(Hh / 16, ny), 128, wvSmem>>>(args, s);
    }

    // FC on tensor cores
    tsplit_k<<<dim3(Hh / 32, Vv / 32), 256>>>(Wfc, Bhi, Blo, Hh, Vv);
    mma_gemm_k<<<dim3(32, Vv / 128), 256, fcSmem>>>(
        Ahi, Alo, Bhi, Blo, bfc, out, Hh, Vv, 1);

    softmax_k<<<Bb * Tt, 256>>>(out);
}

// round 7
// speedup vs baseline: 1.1058x; 1.1058x over previous
#include <cuda_runtime.h>
#include <cuda_bf16.h>

#define Bb 64
#define Tt 64
#define Hh 1024
#define Vv 32000
#define Ee 512
#define WHH (4 * Hh * Hh)

// ---------------- scratch (static device memory; no allocation) ----------------
__device__ float g_xbuf[Tt * Bb * Ee];
__device__ float g_h[8 * Bb * Hh];
__device__ float g_c[4 * Bb * Hh];
__device__ float g_zpre[Tt * Bb * 4 * Hh];
__device__ __nv_bfloat16 g_Ahi[4096 * 1024];
__device__ __nv_bfloat16 g_Alo[4096 * 1024];
__device__ __nv_bfloat16 g_B1hi[4096 * 512];
__device__ __nv_bfloat16 g_B1lo[4096 * 512];
__device__ __nv_bfloat16 g_Bhi[(size_t)Vv * 1024];
__device__ __nv_bfloat16 g_Blo[(size_t)Vv * 1024];
__device__ __nv_bfloat16 g_hsp_hi[8 * Bb * Hh];
__device__ __nv_bfloat16 g_hsp_lo[8 * Bb * Hh];
__device__ __nv_bfloat16 g_Wsp_hi[3 * WHH];
__device__ __nv_bfloat16 g_Wsp_lo[3 * WHH];
__device__ __nv_bfloat16 g_Usp_hi[4 * WHH];
__device__ __nv_bfloat16 g_Usp_lo[4 * WHH];

struct CellArgs {
    const float* b[4];
};

// ---------------- cp.async / mma helpers ----------------------------------------
__device__ __forceinline__ void cp16(void* smem_dst, const void* gsrc) {
    unsigned s = (unsigned)__cvta_generic_to_shared(smem_dst);
    asm volatile("cp.async.cg.shared.global [%0], [%1], 16;\n" :: "r"(s), "l"(gsrc));
}
__device__ __forceinline__ void cp_commit() {
    asm volatile("cp.async.commit_group;\n" ::: "memory");
}
__device__ __forceinline__ void cp_wait2() {
    asm volatile("cp.async.wait_group 2;\n" ::: "memory");
}
__device__ __forceinline__ void cp_wait1() {
    asm volatile("cp.async.wait_group 1;\n" ::: "memory");
}
__device__ __forceinline__ void cp_wait0() {
    asm volatile("cp.async.wait_group 0;\n" ::: "memory");
}
__device__ __forceinline__ void barw(int id) {
    asm volatile("bar.sync %0, 128;" :: "r"(id) : "memory");
}

__device__ __forceinline__ void mma16816(float c[4],
                                         unsigned a0, unsigned a1, unsigned a2, unsigned a3,
                                         unsigned b0, unsigned b1) {
    asm volatile(
        "mma.sync.aligned.m16n8k16.row.col.f32.bf16.bf16.f32 "
        "{%0,%1,%2,%3}, {%4,%5,%6,%7}, {%8,%9}, {%0,%1,%2,%3};"
        : "+f"(c[0]), "+f"(c[1]), "+f"(c[2]), "+f"(c[3])
        : "r"(a0), "r"(a1), "r"(a2), "r"(a3), "r"(b0), "r"(b1));
}

// ---------------- embedding lookup ---------------------------------------------
__global__ __launch_bounds__(256) void embed_k(const int* __restrict__ tok,
                                               const float* __restrict__ emb) {
    int idx = blockIdx.x * 256 + threadIdx.x;
    int e  = idx & (Ee - 1);
    int bt = idx >> 9;
    int b  = bt & (Bb - 1);
    int t  = bt >> 6;
    g_xbuf[idx] = emb[(size_t)tok[b * Tt + t] * Ee + e];
}

// ---------------- fp32 -> (hi, lo) bf16 split ----------------------------------
__global__ __launch_bounds__(256) void split_k(const float* __restrict__ src,
                                               __nv_bfloat16* __restrict__ hi,
                                               __nv_bfloat16* __restrict__ lo, int n) {
    int i = blockIdx.x * 256 + threadIdx.x;
    if (i < n) {
        float x = src[i];
        __nv_bfloat16 h = __float2bfloat16(x);
        hi[i] = h;
        lo[i] = __float2bfloat16(x - __bfloat162float(h));
    }
}

// ---------------- split initial h states ---------------------------------------
__global__ __launch_bounds__(256) void hinit_split_k() {
    int i = blockIdx.x * 256 + threadIdx.x;
    int l = i >> 16;
    int r = i & 65535;
    size_t o = ((size_t)(l * 2)) * (Bb * Hh) + r;
    float x = g_h[o];
    __nv_bfloat16 h = __float2bfloat16(x);
    g_hsp_hi[o] = h;
    g_hsp_lo[o] = __float2bfloat16(x - __bfloat162float(h));
}

// ---------------- transpose + split: src[K][N] -> hi/lo [N][K] ------------------
__global__ __launch_bounds__(256) void tsplit_k(const float* __restrict__ src,
                                                __nv_bfloat16* __restrict__ hi,
                                                __nv_bfloat16* __restrict__ lo,
                                                int K, int N) {
    __shared__ float tile[32][33];
    int k0 = blockIdx.x * 32, n0 = blockIdx.y * 32;
    int tx = threadIdx.x & 31, ty = threadIdx.x >> 5;
#pragma unroll
    for (int j = 0; j < 32; j += 8)
        tile[ty + j][tx] = src[(size_t)(k0 + ty + j) * N + n0 + tx];
    __syncthreads();
#pragma unroll
    for (int j = 0; j < 32; j += 8) {
        float x = tile[tx][ty + j];
        __nv_bfloat16 h = __float2bfloat16(x);
        size_t o = (size_t)(n0 + ty + j) * K + k0 + tx;
        hi[o] = h;
        lo[o] = __float2bfloat16(x - __bfloat162float(h));
    }
}

// ---------------- split-bf16 tensor-core GEMM (round-5 known-good) --------------
__global__ __launch_bounds__(256) void mma_gemm_k(
    const __nv_bfloat16* __restrict__ Ahi, const __nv_bfloat16* __restrict__ Alo,
    const __nv_bfloat16* __restrict__ Bhi, const __nv_bfloat16* __restrict__ Blo,
    const float* __restrict__ bias,
    float* __restrict__ out, int K, int N, int perm)
{
    __shared__ __nv_bfloat16 As[2][128][40];
    __shared__ __nv_bfloat16 Bs[2][128][40];

    const int tid  = threadIdx.x;
    const int row0 = blockIdx.x * 128;
    const int col0 = blockIdx.y * 128;
    const int wid  = tid >> 5, lane = tid & 31;
    const int wm   = wid >> 2;
    const int wn   = wid & 3;
    const int g    = lane >> 2, tg = lane & 3;

    const int kps  = K >> 5;
    const int nit  = 3 * kps;

    float acc[4][4][4];
#pragma unroll
    for (int im = 0; im < 4; im++)
#pragma unroll
        for (int in_ = 0; in_ < 4; in_++)
#pragma unroll
            for (int q = 0; q < 4; q++) acc[im][in_][q] = 0.f;

    const int ca  = tid * 2;
    const int ar0 = ca >> 2,       ao0 = (ca & 3) * 8;
    const int ar1 = (ca + 1) >> 2, ao1 = ((ca + 1) & 3) * 8;

    auto issue = [&](int it, int buf) {
        int s  = (it >= 2 * kps) ? 2 : (it >= kps ? 1 : 0);
        int k0 = (it - s * kps) * 32;
        const __nv_bfloat16* A = (s == 1) ? Alo : Ahi;
        const __nv_bfloat16* B = (s == 2) ? Blo : Bhi;
        cp16(&As[buf][ar0][ao0], A + (size_t)(row0 + ar0) * K + k0 + ao0);
        cp16(&As[buf][ar1][ao1], A + (size_t)(row0 + ar1) * K + k0 + ao1);
        cp16(&Bs[buf][ar0][ao0], B + (size_t)(col0 + ar0) * K + k0 + ao0);
        cp16(&Bs[buf][ar1][ao1], B + (size_t)(col0 + ar1) * K + k0 + ao1);
        cp_commit();
    };

    issue(0, 0);

#pragma unroll 1
    for (int it = 0; it < nit; it++) {
        const int buf = it & 1;
        if (it + 1 < nit) { issue(it + 1, buf ^ 1); cp_wait1(); }
        else              { cp_wait0(); }
        __syncthreads();

#pragma unroll
        for (int kk = 0; kk < 32; kk += 16) {
            unsigned a[4][4], b[4][2];
#pragma unroll
            for (int im = 0; im < 4; im++) {
                int r = wm * 64 + im * 16;
                a[im][0] = *(const unsigned*)&As[buf][r + g][kk + tg * 2];
                a[im][1] = *(const unsigned*)&As[buf][r + g + 8][kk + tg * 2];
                a[im][2] = *(const unsigned*)&As[buf][r + g][kk + tg * 2 + 8];
                a[im][3] = *(const unsigned*)&As[buf][r + g + 8][kk + tg * 2 + 8];
            }
#pragma unroll
            for (int in_ = 0; in_ < 4; in_++) {
                int nn = wn * 32 + in_ * 8 + g;
                b[in_][0] = *(const unsigned*)&Bs[buf][nn][kk + tg * 2];
                b[in_][1] = *(const unsigned*)&Bs[buf][nn][kk + tg * 2 + 8];
            }
#pragma unroll
            for (int im = 0; im < 4; im++)
#pragma unroll
                for (int in_ = 0; in_ < 4; in_++)
                    mma16816(acc[im][in_],
                             a[im][0], a[im][1], a[im][2], a[im][3],
                             b[in_][0], b[in_][1]);
        }
        __syncthreads();
    }

#pragma unroll
    for (int im = 0; im < 4; im++) {
#pragma unroll
        for (int in_ = 0; in_ < 4; in_++) {
            int rr = row0 + wm * 64 + im * 16 + g;
            int cn = col0 + wn * 32 + in_ * 8 + tg * 2;
            float b0v = bias ? bias[cn] : 0.f;
            float b1v = bias ? bias[cn + 1] : 0.f;
#pragma unroll
            for (int half = 0; half < 2; half++) {
                int r = rr + half * 8;
                size_t orow;
                if (perm) {
                    int t = r >> 6, b = r & 63;
                    orow = (size_t)(b * Tt + t);
                } else {
                    orow = (size_t)r;
                }
                float2 v;
                v.x = acc[im][in_][half * 2 + 0] + b0v;
                v.y = acc[im][in_][half * 2 + 1] + b1v;
                *(float2*)(out + orow * N + cn) = v;
            }
        }
    }
}

// ---------------- wavefront LSTM cell: dual warpgroups, split-K -----------------
// 256 threads = 2 warpgroups of 4 warps. Each wg runs its own 3-stage cp.async
// pipeline (private smem buffers, private named barrier) over HALF the K
// iterations; partials combine in the Zs tile. C tile [64 x 64] per block.
#define WLD 40
#define WSTG (64 * WLD)     // elems per tile stage
// dyn smem: wg0 {As0,As1,As2,Bs0,Bs1,Bs2}, wg1 same (12*WSTG bf16), then Zs fp32
__global__ __launch_bounds__(256) void lstm_wave_mma_k(CellArgs args, int s) {
    extern __shared__ __nv_bfloat16 smem[];
    float* Zs = (float*)(smem + 12 * WSTG);       // [64][68]

    const int tid  = threadIdx.x;
    const int wg   = tid >> 7;                    // 0 or 1
    const int wtid = tid & 127;
    __nv_bfloat16* wgbase = smem + wg * 6 * WSTG;

    const int lmin = (s > 63) ? (s - 63) : 0;
    const int l    = lmin + blockIdx.y;
    const int t    = s - l;
    const size_t SH = (size_t)Bb * Hh;
    const int pin  = t & 1, pout = (t + 1) & 1;
    const int j0   = blockIdx.x * 16;

    const __nv_bfloat16* h_hi = g_hsp_hi + (size_t)(l * 2 + pin) * SH;
    const __nv_bfloat16* h_lo = g_hsp_lo + (size_t)(l * 2 + pin) * SH;
    const __nv_bfloat16* Uhi  = g_Usp_hi + (size_t)l * WHH;
    const __nv_bfloat16* Ulo  = g_Usp_lo + (size_t)l * WHH;

    const __nv_bfloat16* Aseg[6];
    const __nv_bfloat16* Bseg[6];
    int nseg;
    if (l == 0) {
        Aseg[0] = h_hi; Bseg[0] = Uhi;
        Aseg[1] = h_lo; Bseg[1] = Uhi;
        Aseg[2] = h_hi; Bseg[2] = Ulo;
        nseg = 3;
    } else {
        const __nv_bfloat16* x_hi = g_hsp_hi + (size_t)((l - 1) * 2 + pout) * SH;
        const __nv_bfloat16* x_lo = g_hsp_lo + (size_t)((l - 1) * 2 + pout) * SH;
        const __nv_bfloat16* Whi  = g_Wsp_hi + (size_t)(l - 1) * WHH;
        const __nv_bfloat16* Wlo  = g_Wsp_lo + (size_t)(l - 1) * WHH;
        Aseg[0] = x_hi; Bseg[0] = Whi;
        Aseg[1] = x_lo; Bseg[1] = Whi;
        Aseg[2] = x_hi; Bseg[2] = Wlo;
        Aseg[3] = h_hi; Bseg[3] = Uhi;
        Aseg[4] = h_lo; Bseg[4] = Uhi;
        Aseg[5] = h_hi; Bseg[5] = Ulo;
        nseg = 6;
    }
    const int nit  = nseg * 32;                   // 32-wide K chunks, K=1024/seg
    const int half = nit >> 1;
    const int it0  = wg * half;
    const int it1  = it0 + half;
    const int bid  = wg + 1;                      // named barrier id

    const int wn   = wtid >> 5;                   // warp's n range within wg
    const int lane = tid & 31;
    const int g    = lane >> 2, tg = lane & 3;

    // cp.async coords within wg: A/B 64 rows x 32 k, 2 threads/row, 2x16B each
    const int arow = wtid >> 1;
    const int aoff = (wtid & 1) * 16;
    const int bgrow = (arow >> 4) * Hh + j0 + (arow & 15);

    float acc[4][2][4];
#pragma unroll
    for (int im = 0; im < 4; im++)
#pragma unroll
        for (int in_ = 0; in_ < 2; in_++)
#pragma unroll
            for (int q = 0; q < 4; q++) acc[im][in_][q] = 0.f;

    auto issue = [&](int it, int buf) {
        int seg = it >> 5;
        int k0  = (it & 31) * 32;
        const __nv_bfloat16* A  = Aseg[seg];
        const __nv_bfloat16* Bp = Bseg[seg];
        __nv_bfloat16* As = wgbase + buf * WSTG;
        __nv_bfloat16* Bs = wgbase + (3 + buf) * WSTG;
        cp16(As + arow * WLD + aoff,     A + (size_t)arow * Hh + k0 + aoff);
        cp16(As + arow * WLD + aoff + 8, A + (size_t)arow * Hh + k0 + aoff + 8);
        cp16(Bs + arow * WLD + aoff,     Bp + (size_t)bgrow * Hh + k0 + aoff);
        cp16(Bs + arow * WLD + aoff + 8, Bp + (size_t)bgrow * Hh + k0 + aoff + 8);
        cp_commit();
    };

    issue(it0, 0);
    issue(it0 + 1, 1);

#pragma unroll 1
    for (int it = it0; it < it1; it++) {
        const int i = it - it0;
        if (it + 2 < it1)      { issue(it + 2, (i + 2) % 3); cp_wait2(); }
        else if (it + 1 < it1) { cp_wait1(); }
        else                   { cp_wait0(); }
        barw(bid);
        const int buf = i % 3;
        const __nv_bfloat16* As = wgbase + buf * WSTG;
        const __nv_bfloat16* Bs = wgbase + (3 + buf) * WSTG;

#pragma unroll
        for (int kk = 0; kk < 32; kk += 16) {
            unsigned a[4][4], b[2][2];
#pragma unroll
            for (int im = 0; im < 4; im++) {
                int r = im * 16;
                a[im][0] = *(const unsigned*)&As[(r + g) * WLD + kk + tg * 2];
                a[im][1] = *(const unsigned*)&As[(r + g + 8) * WLD + kk + tg * 2];
                a[im][2] = *(const unsigned*)&As[(r + g) * WLD + kk + tg * 2 + 8];
                a[im][3] = *(const unsigned*)&As[(r + g + 8) * WLD + kk + tg * 2 + 8];
            }
#pragma unroll
            for (int in_ = 0; in_ < 2; in_++) {
                int nn = wn * 16 + in_ * 8 + g;
                b[in_][0] = *(const unsigned*)&Bs[nn * WLD + kk + tg * 2];
                b[in_][1] = *(const unsigned*)&Bs[nn * WLD + kk + tg * 2 + 8];
            }
#pragma unroll
            for (int im = 0; im < 4; im++)
#pragma unroll
                for (int in_ = 0; in_ < 2; in_++)
                    mma16816(acc[im][in_],
                             a[im][0], a[im][1], a[im][2], a[im][3],
                             b[in_][0], b[in_][1]);
        }
        barw(bid);
    }

    // combine the two warpgroups' partial sums via Zs
    __syncthreads();
    if (wg == 0) {
#pragma unroll
        for (int im = 0; im < 4; im++)
#pragma unroll
            for (int in_ = 0; in_ < 2; in_++)
#pragma unroll
                for (int q = 0; q < 4; q++) {
                    int r = im * 16 + g + ((q >> 1) << 3);
                    int n = wn * 16 + in_ * 8 + tg * 2 + (q & 1);
                    Zs[r * 68 + n] = acc[im][in_][q];
                }
    }
    __syncthreads();
    if (wg == 1) {
#pragma unroll
        for (int im = 0; im < 4; im++)
#pragma unroll
            for (int in_ = 0; in_ < 2; in_++)
#pragma unroll
                for (int q = 0; q < 4; q++) {
                    int r = im * 16 + g + ((q >> 1) << 3);
                    int n = wn * 16 + in_ * 8 + tg * 2 + (q & 1);
                    Zs[r * 68 + n] += acc[im][in_][q];
                }
    }
    __syncthreads();

    // gate epilogue: 64 rows x 16 units = 1024 cells, 4 per thread
    const float* bias = args.b[l];
    float* c = g_c + (size_t)l * SH;
    __nv_bfloat16* ho_hi = g_hsp_hi + (size_t)(l * 2 + pout) * SH;
    __nv_bfloat16* ho_lo = g_hsp_lo + (size_t)(l * 2 + pout) * SH;
    const float* zp = (l == 0) ? (g_zpre + (size_t)t * Bb * 4 * Hh) : nullptr;

#pragma unroll
    for (int q = 0; q < 4; q++) {
        int e  = tid + 256 * q;
        int r  = e >> 4;
        int uu = e & 15;
        int j  = j0 + uu;
        float zi = Zs[r * 68 + uu]      + bias[j];
        float zf = Zs[r * 68 + 16 + uu] + bias[Hh + j];
        float zg = Zs[r * 68 + 32 + uu] + bias[2 * Hh + j];
        float zo = Zs[r * 68 + 48 + uu] + bias[3 * Hh + j];
        if (zp) {
            const float* z = zp + (size_t)r * (4 * Hh);
            zi += z[j]; zf += z[Hh + j]; zg += z[2 * Hh + j]; zo += z[3 * Hh + j];
        }
        float si = 1.f / (1.f + __expf(-zi));
        float sf = 1.f / (1.f + __expf(-zf));
        float so = 1.f / (1.f + __expf(-zo));
        float tg_ = tanhf(zg);
        float cn = sf * c[r * Hh + j] + si * tg_;
        float hn = so * tanhf(cn);
        c[r * Hh + j] = cn;
        __nv_bfloat16 hh = __float2bfloat16(hn);
        float lo = hn - __bfloat162float(hh);
        ho_hi[r * Hh + j] = hh;
        ho_lo[r * Hh + j] = __float2bfloat16(lo);
        if (l == 3) {
            size_t o = ((size_t)t * Bb + r) * Hh + j;
            g_Ahi[o] = hh;
            g_Alo[o] = __float2bfloat16(lo);
        }
    }
}

// ---------------- online softmax (2 reads + 1 write) ----------------------------
__global__ __launch_bounds__(256) void softmax_k(float* __restrict__ out) {
    __shared__ float mred[256], sred[256];
    float* p = out + (size_t)blockIdx.x * Vv;
    int tid = threadIdx.x;

    float m = -3.4e38f, sum = 0.f;
    for (int i = tid; i < Vv; i += 256) {
        float x = p[i];
        float mn = fmaxf(m, x);
        sum = sum * __expf(m - mn) + __expf(x - mn);
        m = mn;
    }
    mred[tid] = m; sred[tid] = sum; __syncthreads();
    for (int st = 128; st > 0; st >>= 1) {
        if (tid < st) {
            float m2 = mred[tid + st], s2 = sred[tid + st];
            float mn = fmaxf(mred[tid], m2);
            sred[tid] = sred[tid] * __expf(mred[tid] - mn) + s2 * __expf(m2 - mn);
            mred[tid] = mn;
        }
        __syncthreads();
    }
    float M = mred[0];
    float inv = 1.f / sred[0];
    for (int i = tid; i < Vv; i += 256) p[i] = __expf(p[i] - M) * inv;
}

// ---------------- launch ------------------------------------------------------
extern "C" void kernel_launch(void* const* d_in, const int* in_sizes, int n_in,
                              void* d_out, int out_size) {
    (void)in_sizes; (void)n_in; (void)out_size;
    const int*   tok = (const int*)d_in[0];
    const float* emb = (const float*)d_in[9];
    const float* W[4]; const float* U[4];
    CellArgs args;
    for (int l = 0; l < 4; l++) {
        W[l] = (const float*)d_in[10 + 3 * l];
        U[l] = (const float*)d_in[11 + 3 * l];
        args.b[l] = (const float*)d_in[12 + 3 * l];
    }
    const float* Wfc = (const float*)d_in[22];
    const float* bfc = (const float*)d_in[23];
    float* out = (float*)d_out;

    float *xbuf, *hbuf, *cbuf, *zpre;
    __nv_bfloat16 *Ahi, *Alo, *B1hi, *B1lo, *Bhi, *Blo, *Wsph, *Wspl, *Usph, *Uspl;
    cudaGetSymbolAddress((void**)&xbuf, g_xbuf);
    cudaGetSymbolAddress((void**)&hbuf, g_h);
    cudaGetSymbolAddress((void**)&cbuf, g_c);
    cudaGetSymbolAddress((void**)&zpre, g_zpre);
    cudaGetSymbolAddress((void**)&Ahi,  g_Ahi);
    cudaGetSymbolAddress((void**)&Alo,  g_Alo);
    cudaGetSymbolAddress((void**)&B1hi, g_B1hi);
    cudaGetSymbolAddress((void**)&B1lo, g_B1lo);
    cudaGetSymbolAddress((void**)&Bhi,  g_Bhi);
    cudaGetSymbolAddress((void**)&Blo,  g_Blo);
    cudaGetSymbolAddress((void**)&Wsph, g_Wsp_hi);
    cudaGetSymbolAddress((void**)&Wspl, g_Wsp_lo);
    cudaGetSymbolAddress((void**)&Usph, g_Usp_hi);
    cudaGetSymbolAddress((void**)&Uspl, g_Usp_lo);

    // dynamic smem for the wave kernel: 12 pipeline stages + Zs
    const int wvSmem = 12 * WSTG * 2 + 64 * 68 * 4;   // 61440 + 17408 = 78848 B
    cudaFuncSetAttribute(lstm_wave_mma_k,
                         cudaFuncAttributeMaxDynamicSharedMemorySize, wvSmem);

    const size_t SH = (size_t)Bb * Hh;

    for (int l = 0; l < 4; l++) {
        cudaMemcpyAsync(hbuf + (size_t)(l * 2) * SH, d_in[1 + 2 * l],
                        SH * sizeof(float), cudaMemcpyDeviceToDevice, 0);
        cudaMemcpyAsync(cbuf + (size_t)l * SH, d_in[2 + 2 * l],
                        SH * sizeof(float), cudaMemcpyDeviceToDevice, 0);
    }

    embed_k<<<(Tt * Bb * Ee) / 256, 256>>>(tok, emb);
    hinit_split_k<<<(4 * Bb * Hh) / 256, 256>>>();

    // zpre = x @ W1 on tensor cores
    split_k<<<(4096 * 512) / 256, 256>>>(xbuf, Ahi, Alo, 4096 * 512);
    tsplit_k<<<dim3(Ee / 32, (4 * Hh) / 32), 256>>>(W[0], B1hi, B1lo, Ee, 4 * Hh);
    mma_gemm_k<<<dim3(32, (4 * Hh) / 128), 256>>>(
        Ahi, Alo, B1hi, B1lo, nullptr, zpre, Ee, 4 * Hh, 0);

    // transpose+split recurrent weights
    for (int l = 1; l < 4; l++)
        tsplit_k<<<dim3(Hh / 32, (4 * Hh) / 32), 256>>>(
            W[l], Wsph + (size_t)(l - 1) * WHH, Wspl + (size_t)(l - 1) * WHH,
            Hh, 4 * Hh);
    for (int l = 0; l < 4; l++)
        tsplit_k<<<dim3(Hh / 32, (4 * Hh) / 32), 256>>>(
            U[l], Usph + (size_t)l * WHH, Uspl + (size_t)l * WHH, Hh, 4 * Hh);

    // wavefront over diagonals
    for (int s = 0; s <= Tt + 3 - 1; s++) {
        int lmin = (s > Tt - 1) ? (s - (Tt - 1)) : 0;
        int lmax = (s < 3) ? s : 3;
        int ny   = lmax - lmin + 1;
        lstm_wave_mma_k<<<dim3(Hh / 16, ny), 256, wvSmem>>>(args, s);
    }

    // FC on tensor cores
    tsplit_k<<<dim3(Hh / 32, Vv / 32), 256>>>(Wfc, Bhi, Blo, Hh, Vv);
    mma_gemm_k<<<dim3(32, Vv / 128), 256>>>(
        Ahi, Alo, Bhi, Blo, bfc, out, Hh, Vv, 1);

    softmax_k<<<Bb * Tt, 256>>>(out);
}

// round 8
// speedup vs baseline: 1.1303x; 1.0222x over previous
#include <cuda_runtime.h>
#include <cuda_bf16.h>

#define Bb 64
#define Tt 64
#define Hh 1024
#define Vv 32000
#define Ee 512
#define WHH (4 * Hh * Hh)

// ---------------- scratch (static device memory; no allocation) ----------------
__device__ float g_xbuf[Tt * Bb * Ee];
__device__ float g_h[8 * Bb * Hh];
__device__ float g_c[4 * Bb * Hh];
__device__ float g_zpre[Tt * Bb * 4 * Hh];
__device__ __nv_bfloat16 g_Ahi[4096 * 1024];
__device__ __nv_bfloat16 g_Alo[4096 * 1024];
__device__ __nv_bfloat16 g_B1hi[4096 * 512];
__device__ __nv_bfloat16 g_B1lo[4096 * 512];
__device__ __nv_bfloat16 g_Bhi[(size_t)Vv * 1024];
__device__ __nv_bfloat16 g_Blo[(size_t)Vv * 1024];
__device__ __nv_bfloat16 g_hsp_hi[8 * Bb * Hh];
__device__ __nv_bfloat16 g_hsp_lo[8 * Bb * Hh];
__device__ __nv_bfloat16 g_Wsp_hi[3 * WHH];
__device__ __nv_bfloat16 g_Wsp_lo[3 * WHH];
__device__ __nv_bfloat16 g_Usp_hi[4 * WHH];
__device__ __nv_bfloat16 g_Usp_lo[4 * WHH];

struct CellArgs {
    const float* b[4];
};

// ---------------- cp.async / mma helpers ----------------------------------------
__device__ __forceinline__ void cp16(void* smem_dst, const void* gsrc) {
    unsigned s = (unsigned)__cvta_generic_to_shared(smem_dst);
    asm volatile("cp.async.cg.shared.global [%0], [%1], 16;\n" :: "r"(s), "l"(gsrc));
}
__device__ __forceinline__ void cp_commit() {
    asm volatile("cp.async.commit_group;\n" ::: "memory");
}
__device__ __forceinline__ void cp_wait2() {
    asm volatile("cp.async.wait_group 2;\n" ::: "memory");
}
__device__ __forceinline__ void cp_wait1() {
    asm volatile("cp.async.wait_group 1;\n" ::: "memory");
}
__device__ __forceinline__ void cp_wait0() {
    asm volatile("cp.async.wait_group 0;\n" ::: "memory");
}
__device__ __forceinline__ void barw(int id) {
    asm volatile("bar.sync %0, 128;" :: "r"(id) : "memory");
}

__device__ __forceinline__ void mma16816(float c[4],
                                         unsigned a0, unsigned a1, unsigned a2, unsigned a3,
                                         unsigned b0, unsigned b1) {
    asm volatile(
        "mma.sync.aligned.m16n8k16.row.col.f32.bf16.bf16.f32 "
        "{%0,%1,%2,%3}, {%4,%5,%6,%7}, {%8,%9}, {%0,%1,%2,%3};"
        : "+f"(c[0]), "+f"(c[1]), "+f"(c[2]), "+f"(c[3])
        : "r"(a0), "r"(a1), "r"(a2), "r"(a3), "r"(b0), "r"(b1));
}

// ---------------- embedding lookup ---------------------------------------------
__global__ __launch_bounds__(256) void embed_k(const int* __restrict__ tok,
                                               const float* __restrict__ emb) {
    int idx = blockIdx.x * 256 + threadIdx.x;
    int e  = idx & (Ee - 1);
    int bt = idx >> 9;
    int b  = bt & (Bb - 1);
    int t  = bt >> 6;
    g_xbuf[idx] = emb[(size_t)tok[b * Tt + t] * Ee + e];
}

// ---------------- fp32 -> (hi, lo) bf16 split ----------------------------------
__global__ __launch_bounds__(256) void split_k(const float* __restrict__ src,
                                               __nv_bfloat16* __restrict__ hi,
                                               __nv_bfloat16* __restrict__ lo, int n) {
    int i = blockIdx.x * 256 + threadIdx.x;
    if (i < n) {
        float x = src[i];
        __nv_bfloat16 h = __float2bfloat16(x);
        hi[i] = h;
        lo[i] = __float2bfloat16(x - __bfloat162float(h));
    }
}

// ---------------- split initial h states ---------------------------------------
__global__ __launch_bounds__(256) void hinit_split_k() {
    int i = blockIdx.x * 256 + threadIdx.x;
    int l = i >> 16;
    int r = i & 65535;
    size_t o = ((size_t)(l * 2)) * (Bb * Hh) + r;
    float x = g_h[o];
    __nv_bfloat16 h = __float2bfloat16(x);
    g_hsp_hi[o] = h;
    g_hsp_lo[o] = __float2bfloat16(x - __bfloat162float(h));
}

// ---------------- transpose + split: src[K][N] -> hi/lo [N][K] ------------------
__global__ __launch_bounds__(256) void tsplit_k(const float* __restrict__ src,
                                                __nv_bfloat16* __restrict__ hi,
                                                __nv_bfloat16* __restrict__ lo,
                                                int K, int N) {
    __shared__ float tile[32][33];
    int k0 = blockIdx.x * 32, n0 = blockIdx.y * 32;
    int tx = threadIdx.x & 31, ty = threadIdx.x >> 5;
#pragma unroll
    for (int j = 0; j < 32; j += 8)
        tile[ty + j][tx] = src[(size_t)(k0 + ty + j) * N + n0 + tx];
    __syncthreads();
#pragma unroll
    for (int j = 0; j < 32; j += 8) {
        float x = tile[tx][ty + j];
        __nv_bfloat16 h = __float2bfloat16(x);
        size_t o = (size_t)(n0 + ty + j) * K + k0 + tx;
        hi[o] = h;
        lo[o] = __float2bfloat16(x - __bfloat162float(h));
    }
}

// ---------------- split-bf16 tensor-core GEMM (known-good, + rowbase) -----------
__global__ __launch_bounds__(256) void mma_gemm_k(
    const __nv_bfloat16* __restrict__ Ahi, const __nv_bfloat16* __restrict__ Alo,
    const __nv_bfloat16* __restrict__ Bhi, const __nv_bfloat16* __restrict__ Blo,
    const float* __restrict__ bias,
    float* __restrict__ out, int K, int N, int perm, int rowbase)
{
    __shared__ __nv_bfloat16 As[2][128][40];
    __shared__ __nv_bfloat16 Bs[2][128][40];

    const int tid  = threadIdx.x;
    const int row0 = rowbase + blockIdx.x * 128;
    const int col0 = blockIdx.y * 128;
    const int wid  = tid >> 5, lane = tid & 31;
    const int wm   = wid >> 2;
    const int wn   = wid & 3;
    const int g    = lane >> 2, tg = lane & 3;

    const int kps  = K >> 5;
    const int nit  = 3 * kps;

    float acc[4][4][4];
#pragma unroll
    for (int im = 0; im < 4; im++)
#pragma unroll
        for (int in_ = 0; in_ < 4; in_++)
#pragma unroll
            for (int q = 0; q < 4; q++) acc[im][in_][q] = 0.f;

    const int ca  = tid * 2;
    const int ar0 = ca >> 2,       ao0 = (ca & 3) * 8;
    const int ar1 = (ca + 1) >> 2, ao1 = ((ca + 1) & 3) * 8;

    auto issue = [&](int it, int buf) {
        int s  = (it >= 2 * kps) ? 2 : (it >= kps ? 1 : 0);
        int k0 = (it - s * kps) * 32;
        const __nv_bfloat16* A = (s == 1) ? Alo : Ahi;
        const __nv_bfloat16* B = (s == 2) ? Blo : Bhi;
        cp16(&As[buf][ar0][ao0], A + (size_t)(row0 + ar0) * K + k0 + ao0);
        cp16(&As[buf][ar1][ao1], A + (size_t)(row0 + ar1) * K + k0 + ao1);
        cp16(&Bs[buf][ar0][ao0], B + (size_t)(col0 + ar0) * K + k0 + ao0);
        cp16(&Bs[buf][ar1][ao1], B + (size_t)(col0 + ar1) * K + k0 + ao1);
        cp_commit();
    };

    issue(0, 0);

#pragma unroll 1
    for (int it = 0; it < nit; it++) {
        const int buf = it & 1;
        if (it + 1 < nit) { issue(it + 1, buf ^ 1); cp_wait1(); }
        else              { cp_wait0(); }
        __syncthreads();

#pragma unroll
        for (int kk = 0; kk < 32; kk += 16) {
            unsigned a[4][4], b[4][2];
#pragma unroll
            for (int im = 0; im < 4; im++) {
                int r = wm * 64 + im * 16;
                a[im][0] = *(const unsigned*)&As[buf][r + g][kk + tg * 2];
                a[im][1] = *(const unsigned*)&As[buf][r + g + 8][kk + tg * 2];
                a[im][2] = *(const unsigned*)&As[buf][r + g][kk + tg * 2 + 8];
                a[im][3] = *(const unsigned*)&As[buf][r + g + 8][kk + tg * 2 + 8];
            }
#pragma unroll
            for (int in_ = 0; in_ < 4; in_++) {
                int nn = wn * 32 + in_ * 8 + g;
                b[in_][0] = *(const unsigned*)&Bs[buf][nn][kk + tg * 2];
                b[in_][1] = *(const unsigned*)&Bs[buf][nn][kk + tg * 2 + 8];
            }
#pragma unroll
            for (int im = 0; im < 4; im++)
#pragma unroll
                for (int in_ = 0; in_ < 4; in_++)
                    mma16816(acc[im][in_],
                             a[im][0], a[im][1], a[im][2], a[im][3],
                             b[in_][0], b[in_][1]);
        }
        __syncthreads();
    }

#pragma unroll
    for (int im = 0; im < 4; im++) {
#pragma unroll
        for (int in_ = 0; in_ < 4; in_++) {
            int rr = row0 + wm * 64 + im * 16 + g;
            int cn = col0 + wn * 32 + in_ * 8 + tg * 2;
            float b0v = bias ? bias[cn] : 0.f;
            float b1v = bias ? bias[cn + 1] : 0.f;
#pragma unroll
            for (int half = 0; half < 2; half++) {
                int r = rr + half * 8;
                size_t orow;
                if (perm) {
                    int t = r >> 6, b = r & 63;
                    orow = (size_t)(b * Tt + t);
                } else {
                    orow = (size_t)r;
                }
                float2 v;
                v.x = acc[im][in_][half * 2 + 0] + b0v;
                v.y = acc[im][in_][half * 2 + 1] + b1v;
                *(float2*)(out + orow * N + cn) = v;
            }
        }
    }
}

// ---------------- wavefront LSTM cell: dual warpgroups, split-K (round-7 best) --
#define WLD 40
#define WSTG (64 * WLD)
__global__ __launch_bounds__(256) void lstm_wave_mma_k(CellArgs args, int s) {
    extern __shared__ __nv_bfloat16 smem[];
    float* Zs = (float*)(smem + 12 * WSTG);

    const int tid  = threadIdx.x;
    const int wg   = tid >> 7;
    const int wtid = tid & 127;
    __nv_bfloat16* wgbase = smem + wg * 6 * WSTG;

    const int lmin = (s > 63) ? (s - 63) : 0;
    const int l    = lmin + blockIdx.y;
    const int t    = s - l;
    const size_t SH = (size_t)Bb * Hh;
    const int pin  = t & 1, pout = (t + 1) & 1;
    const int j0   = blockIdx.x * 16;

    const __nv_bfloat16* h_hi = g_hsp_hi + (size_t)(l * 2 + pin) * SH;
    const __nv_bfloat16* h_lo = g_hsp_lo + (size_t)(l * 2 + pin) * SH;
    const __nv_bfloat16* Uhi  = g_Usp_hi + (size_t)l * WHH;
    const __nv_bfloat16* Ulo  = g_Usp_lo + (size_t)l * WHH;

    const __nv_bfloat16* Aseg[6];
    const __nv_bfloat16* Bseg[6];
    int nseg;
    if (l == 0) {
        Aseg[0] = h_hi; Bseg[0] = Uhi;
        Aseg[1] = h_lo; Bseg[1] = Uhi;
        Aseg[2] = h_hi; Bseg[2] = Ulo;
        nseg = 3;
    } else {
        const __nv_bfloat16* x_hi = g_hsp_hi + (size_t)((l - 1) * 2 + pout) * SH;
        const __nv_bfloat16* x_lo = g_hsp_lo + (size_t)((l - 1) * 2 + pout) * SH;
        const __nv_bfloat16* Whi  = g_Wsp_hi + (size_t)(l - 1) * WHH;
        const __nv_bfloat16* Wlo  = g_Wsp_lo + (size_t)(l - 1) * WHH;
        Aseg[0] = x_hi; Bseg[0] = Whi;
        Aseg[1] = x_lo; Bseg[1] = Whi;
        Aseg[2] = x_hi; Bseg[2] = Wlo;
        Aseg[3] = h_hi; Bseg[3] = Uhi;
        Aseg[4] = h_lo; Bseg[4] = Uhi;
        Aseg[5] = h_hi; Bseg[5] = Ulo;
        nseg = 6;
    }
    const int nit  = nseg * 32;
    const int half = nit >> 1;
    const int it0  = wg * half;
    const int it1  = it0 + half;
    const int bid  = wg + 1;

    const int wn   = wtid >> 5;
    const int lane = tid & 31;
    const int g    = lane >> 2, tg = lane & 3;

    const int arow = wtid >> 1;
    const int aoff = (wtid & 1) * 16;
    const int bgrow = (arow >> 4) * Hh + j0 + (arow & 15);

    float acc[4][2][4];
#pragma unroll
    for (int im = 0; im < 4; im++)
#pragma unroll
        for (int in_ = 0; in_ < 2; in_++)
#pragma unroll
            for (int q = 0; q < 4; q++) acc[im][in_][q] = 0.f;

    auto issue = [&](int it, int buf) {
        int seg = it >> 5;
        int k0  = (it & 31) * 32;
        const __nv_bfloat16* A  = Aseg[seg];
        const __nv_bfloat16* Bp = Bseg[seg];
        __nv_bfloat16* As = wgbase + buf * WSTG;
        __nv_bfloat16* Bs = wgbase + (3 + buf) * WSTG;
        cp16(As + arow * WLD + aoff,     A + (size_t)arow * Hh + k0 + aoff);
        cp16(As + arow * WLD + aoff + 8, A + (size_t)arow * Hh + k0 + aoff + 8);
        cp16(Bs + arow * WLD + aoff,     Bp + (size_t)bgrow * Hh + k0 + aoff);
        cp16(Bs + arow * WLD + aoff + 8, Bp + (size_t)bgrow * Hh + k0 + aoff + 8);
        cp_commit();
    };

    issue(it0, 0);
    issue(it0 + 1, 1);

#pragma unroll 1
    for (int it = it0; it < it1; it++) {
        const int i = it - it0;
        if (it + 2 < it1)      { issue(it + 2, (i + 2) % 3); cp_wait2(); }
        else if (it + 1 < it1) { cp_wait1(); }
        else                   { cp_wait0(); }
        barw(bid);
        const int buf = i % 3;
        const __nv_bfloat16* As = wgbase + buf * WSTG;
        const __nv_bfloat16* Bs = wgbase + (3 + buf) * WSTG;

#pragma unroll
        for (int kk = 0; kk < 32; kk += 16) {
            unsigned a[4][4], b[2][2];
#pragma unroll
            for (int im = 0; im < 4; im++) {
                int r = im * 16;
                a[im][0] = *(const unsigned*)&As[(r + g) * WLD + kk + tg * 2];
                a[im][1] = *(const unsigned*)&As[(r + g + 8) * WLD + kk + tg * 2];
                a[im][2] = *(const unsigned*)&As[(r + g) * WLD + kk + tg * 2 + 8];
                a[im][3] = *(const unsigned*)&As[(r + g + 8) * WLD + kk + tg * 2 + 8];
            }
#pragma unroll
            for (int in_ = 0; in_ < 2; in_++) {
                int nn = wn * 16 + in_ * 8 + g;
                b[in_][0] = *(const unsigned*)&Bs[nn * WLD + kk + tg * 2];
                b[in_][1] = *(const unsigned*)&Bs[nn * WLD + kk + tg * 2 + 8];
            }
#pragma unroll
            for (int im = 0; im < 4; im++)
#pragma unroll
                for (int in_ = 0; in_ < 2; in_++)
                    mma16816(acc[im][in_],
                             a[im][0], a[im][1], a[im][2], a[im][3],
                             b[in_][0], b[in_][1]);
        }
        barw(bid);
    }

    __syncthreads();
    if (wg == 0) {
#pragma unroll
        for (int im = 0; im < 4; im++)
#pragma unroll
            for (int in_ = 0; in_ < 2; in_++)
#pragma unroll
                for (int q = 0; q < 4; q++) {
                    int r = im * 16 + g + ((q >> 1) << 3);
                    int n = wn * 16 + in_ * 8 + tg * 2 + (q & 1);
                    Zs[r * 68 + n] = acc[im][in_][q];
                }
    }
    __syncthreads();
    if (wg == 1) {
#pragma unroll
        for (int im = 0; im < 4; im++)
#pragma unroll
            for (int in_ = 0; in_ < 2; in_++)
#pragma unroll
                for (int q = 0; q < 4; q++) {
                    int r = im * 16 + g + ((q >> 1) << 3);
                    int n = wn * 16 + in_ * 8 + tg * 2 + (q & 1);
                    Zs[r * 68 + n] += acc[im][in_][q];
                }
    }
    __syncthreads();

    const float* bias = args.b[l];
    float* c = g_c + (size_t)l * SH;
    __nv_bfloat16* ho_hi = g_hsp_hi + (size_t)(l * 2 + pout) * SH;
    __nv_bfloat16* ho_lo = g_hsp_lo + (size_t)(l * 2 + pout) * SH;
    const float* zp = (l == 0) ? (g_zpre + (size_t)t * Bb * 4 * Hh) : nullptr;

#pragma unroll
    for (int q = 0; q < 4; q++) {
        int e  = tid + 256 * q;
        int r  = e >> 4;
        int uu = e & 15;
        int j  = j0 + uu;
        float zi = Zs[r * 68 + uu]      + bias[j];
        float zf = Zs[r * 68 + 16 + uu] + bias[Hh + j];
        float zg = Zs[r * 68 + 32 + uu] + bias[2 * Hh + j];
        float zo = Zs[r * 68 + 48 + uu] + bias[3 * Hh + j];
        if (zp) {
            const float* z = zp + (size_t)r * (4 * Hh);
            zi += z[j]; zf += z[Hh + j]; zg += z[2 * Hh + j]; zo += z[3 * Hh + j];
        }
        float si = 1.f / (1.f + __expf(-zi));
        float sf = 1.f / (1.f + __expf(-zf));
        float so = 1.f / (1.f + __expf(-zo));
        float tg_ = tanhf(zg);
        float cn = sf * c[r * Hh + j] + si * tg_;
        float hn = so * tanhf(cn);
        c[r * Hh + j] = cn;
        __nv_bfloat16 hh = __float2bfloat16(hn);
        float lo = hn - __bfloat162float(hh);
        ho_hi[r * Hh + j] = hh;
        ho_lo[r * Hh + j] = __float2bfloat16(lo);
        if (l == 3) {
            size_t o = ((size_t)t * Bb + r) * Hh + j;
            g_Ahi[o] = hh;
            g_Alo[o] = __float2bfloat16(lo);
        }
    }
}

// ---------------- online softmax, chunked over t --------------------------------
// grid = 64 * 16 blocks; block handles row (b, t0 + (blockIdx.x & 15)).
__global__ __launch_bounds__(256) void softmax_k(float* __restrict__ out, int t0) {
    __shared__ float mred[256], sred[256];
    int row = (blockIdx.x >> 4) * Tt + t0 + (blockIdx.x & 15);
    float* p = out + (size_t)row * Vv;
    int tid = threadIdx.x;

    float m = -3.4e38f, sum = 0.f;
    for (int i = tid; i < Vv; i += 256) {
        float x = p[i];
        float mn = fmaxf(m, x);
        sum = sum * __expf(m - mn) + __expf(x - mn);
        m = mn;
    }
    mred[tid] = m; sred[tid] = sum; __syncthreads();
    for (int st = 128; st > 0; st >>= 1) {
        if (tid < st) {
            float m2 = mred[tid + st], s2 = sred[tid + st];
            float mn = fmaxf(mred[tid], m2);
            sred[tid] = sred[tid] * __expf(mred[tid] - mn) + s2 * __expf(m2 - mn);
            mred[tid] = mn;
        }
        __syncthreads();
    }
    float M = mred[0];
    float inv = 1.f / sred[0];
    for (int i = tid; i < Vv; i += 256) p[i] = __expf(p[i] - M) * inv;
}

// ---------------- launch ------------------------------------------------------
extern "C" void kernel_launch(void* const* d_in, const int* in_sizes, int n_in,
                              void* d_out, int out_size) {
    (void)in_sizes; (void)n_in; (void)out_size;
    const int*   tok = (const int*)d_in[0];
    const float* emb = (const float*)d_in[9];
    const float* W[4]; const float* U[4];
    CellArgs args;
    for (int l = 0; l < 4; l++) {
        W[l] = (const float*)d_in[10 + 3 * l];
        U[l] = (const float*)d_in[11 + 3 * l];
        args.b[l] = (const float*)d_in[12 + 3 * l];
    }
    const float* Wfc = (const float*)d_in[22];
    const float* bfc = (const float*)d_in[23];
    float* out = (float*)d_out;

    float *xbuf, *hbuf, *cbuf, *zpre;
    __nv_bfloat16 *Ahi, *Alo, *B1hi, *B1lo, *Bhi, *Blo, *Wsph, *Wspl, *Usph, *Uspl;
    cudaGetSymbolAddress((void**)&xbuf, g_xbuf);
    cudaGetSymbolAddress((void**)&hbuf, g_h);
    cudaGetSymbolAddress((void**)&cbuf, g_c);
    cudaGetSymbolAddress((void**)&zpre, g_zpre);
    cudaGetSymbolAddress((void**)&Ahi,  g_Ahi);
    cudaGetSymbolAddress((void**)&Alo,  g_Alo);
    cudaGetSymbolAddress((void**)&B1hi, g_B1hi);
    cudaGetSymbolAddress((void**)&B1lo, g_B1lo);
    cudaGetSymbolAddress((void**)&Bhi,  g_Bhi);
    cudaGetSymbolAddress((void**)&Blo,  g_Blo);
    cudaGetSymbolAddress((void**)&Wsph, g_Wsp_hi);
    cudaGetSymbolAddress((void**)&Wspl, g_Wsp_lo);
    cudaGetSymbolAddress((void**)&Usph, g_Usp_hi);
    cudaGetSymbolAddress((void**)&Uspl, g_Usp_lo);

    const int wvSmem = 12 * WSTG * 2 + 64 * 68 * 4;
    cudaFuncSetAttribute(lstm_wave_mma_k,
                         cudaFuncAttributeMaxDynamicSharedMemorySize, wvSmem);

    // side stream + events: created once on the first (non-capture) call
    static cudaStream_t s2 = nullptr;
    static cudaEvent_t evF, evD[4], evJ;
    if (!s2) {
        cudaStreamCreateWithFlags(&s2, cudaStreamNonBlocking);
        cudaEventCreateWithFlags(&evF, cudaEventDisableTiming);
        for (int k = 0; k < 4; k++)
            cudaEventCreateWithFlags(&evD[k], cudaEventDisableTiming);
        cudaEventCreateWithFlags(&evJ, cudaEventDisableTiming);
    }

    const size_t SH = (size_t)Bb * Hh;

    for (int l = 0; l < 4; l++) {
        cudaMemcpyAsync(hbuf + (size_t)(l * 2) * SH, d_in[1 + 2 * l],
                        SH * sizeof(float), cudaMemcpyDeviceToDevice, 0);
        cudaMemcpyAsync(cbuf + (size_t)l * SH, d_in[2 + 2 * l],
                        SH * sizeof(float), cudaMemcpyDeviceToDevice, 0);
    }

    // fork side stream: Wfc transpose+split overlaps everything below
    cudaEventRecord(evF, 0);
    cudaStreamWaitEvent(s2, evF, 0);
    tsplit_k<<<dim3(Hh / 32, Vv / 32), 256, 0, s2>>>(Wfc, Bhi, Blo, Hh, Vv);

    embed_k<<<(Tt * Bb * Ee) / 256, 256>>>(tok, emb);
    hinit_split_k<<<(4 * Bb * Hh) / 256, 256>>>();

    // zpre = x @ W1 on tensor cores
    split_k<<<(4096 * 512) / 256, 256>>>(xbuf, Ahi, Alo, 4096 * 512);
    tsplit_k<<<dim3(Ee / 32, (4 * Hh) / 32), 256>>>(W[0], B1hi, B1lo, Ee, 4 * Hh);
    mma_gemm_k<<<dim3(32, (4 * Hh) / 128), 256>>>(
        Ahi, Alo, B1hi, B1lo, nullptr, zpre, Ee, 4 * Hh, 0, 0);

    // transpose+split recurrent weights
    for (int l = 1; l < 4; l++)
        tsplit_k<<<dim3(Hh / 32, (4 * Hh) / 32), 256>>>(
            W[l], Wsph + (size_t)(l - 1) * WHH, Wspl + (size_t)(l - 1) * WHH,
            Hh, 4 * Hh);
    for (int l = 0; l < 4; l++)
        tsplit_k<<<dim3(Hh / 32, (4 * Hh) / 32), 256>>>(
            U[l], Usph + (size_t)l * WHH, Uspl + (size_t)l * WHH, Hh, 4 * Hh);

    // wavefront over diagonals; FC+softmax chunks overlap on s2
    for (int s = 0; s <= Tt + 3 - 1; s++) {
        int lmin = (s > Tt - 1) ? (s - (Tt - 1)) : 0;
        int lmax = (s < 3) ? s : 3;
        int ny   = lmax - lmin + 1;
        lstm_wave_mma_k<<<dim3(Hh / 16, ny), 256, wvSmem>>>(args, s);
        // h4 rows for t in [16k, 16k+16) complete at diagonal 16k+18 (chunk 3: 66)
        if (s == 18) cudaEventRecord(evD[0], 0);
        if (s == 34) cudaEventRecord(evD[1], 0);
        if (s == 50) cudaEventRecord(evD[2], 0);
        if (s == 66) cudaEventRecord(evD[3], 0);
    }

    // FC + softmax in 4 row-chunks on the side stream
    for (int k = 0; k < 4; k++) {
        cudaStreamWaitEvent(s2, evD[k], 0);
        mma_gemm_k<<<dim3(8, Vv / 128), 256, 0, s2>>>(
            Ahi, Alo, Bhi, Blo, bfc, out, Hh, Vv, 1, k * 1024);
        softmax_k<<<Bb * 16, 256, 0, s2>>>(out, k * 16);
    }
    cudaEventRecord(evJ, s2);
    cudaStreamWaitEvent(0, evJ, 0);
}

// round 9
// speedup vs baseline: 1.4638x; 1.2950x over previous
#include <cuda_runtime.h>
#include <cuda_bf16.h>

#define Bb 64
#define Tt 64
#define Hh 1024
#define Vv 32000
#define Ee 512
#define WHH (4 * Hh * Hh)

// ---------------- scratch (static device memory; no allocation) ----------------
__device__ float g_xbuf[Tt * Bb * Ee];
__device__ float g_h[8 * Bb * Hh];
__device__ float g_c[4 * Bb * Hh];
__device__ float g_zpre[Tt * Bb * 4 * Hh];
__device__ __nv_bfloat16 g_Ahi[4096 * 1024];
__device__ __nv_bfloat16 g_Alo[4096 * 1024];
__device__ __nv_bfloat16 g_B1hi[4096 * 512];
__device__ __nv_bfloat16 g_B1lo[4096 * 512];
__device__ __nv_bfloat16 g_Bhi[(size_t)Vv * 1024];
__device__ __nv_bfloat16 g_Blo[(size_t)Vv * 1024];
__device__ __nv_bfloat16 g_hsp_hi[8 * Bb * Hh];
__device__ __nv_bfloat16 g_hsp_lo[8 * Bb * Hh];
__device__ __nv_bfloat16 g_Wsp_hi[3 * WHH];
__device__ __nv_bfloat16 g_Wsp_lo[3 * WHH];
__device__ __nv_bfloat16 g_Usp_hi[4 * WHH];
__device__ __nv_bfloat16 g_Usp_lo[4 * WHH];

struct CellArgs {
    const float* b[4];
};

// ---------------- cp.async / mma helpers ----------------------------------------
__device__ __forceinline__ void cp16(void* smem_dst, const void* gsrc) {
    unsigned s = (unsigned)__cvta_generic_to_shared(smem_dst);
    asm volatile("cp.async.cg.shared.global [%0], [%1], 16;\n" :: "r"(s), "l"(gsrc));
}
__device__ __forceinline__ void cp_commit() {
    asm volatile("cp.async.commit_group;\n" ::: "memory");
}
__device__ __forceinline__ void cp_wait1() {
    asm volatile("cp.async.wait_group 1;\n" ::: "memory");
}
__device__ __forceinline__ void cp_wait0() {
    asm volatile("cp.async.wait_group 0;\n" ::: "memory");
}
__device__ __forceinline__ void barw(int id) {
    asm volatile("bar.sync %0, 128;" :: "r"(id) : "memory");
}

__device__ __forceinline__ void mma16816(float c[4],
                                         unsigned a0, unsigned a1, unsigned a2, unsigned a3,
                                         unsigned b0, unsigned b1) {
    asm volatile(
        "mma.sync.aligned.m16n8k16.row.col.f32.bf16.bf16.f32 "
        "{%0,%1,%2,%3}, {%4,%5,%6,%7}, {%8,%9}, {%0,%1,%2,%3};"
        : "+f"(c[0]), "+f"(c[1]), "+f"(c[2]), "+f"(c[3])
        : "r"(a0), "r"(a1), "r"(a2), "r"(a3), "r"(b0), "r"(b1));
}

// ---------------- embedding lookup ---------------------------------------------
__global__ __launch_bounds__(256) void embed_k(const int* __restrict__ tok,
                                               const float* __restrict__ emb) {
    int idx = blockIdx.x * 256 + threadIdx.x;
    int e  = idx & (Ee - 1);
    int bt = idx >> 9;
    int b  = bt & (Bb - 1);
    int t  = bt >> 6;
    g_xbuf[idx] = emb[(size_t)tok[b * Tt + t] * Ee + e];
}

// ---------------- fp32 -> (hi, lo) bf16 split ----------------------------------
__global__ __launch_bounds__(256) void split_k(const float* __restrict__ src,
                                               __nv_bfloat16* __restrict__ hi,
                                               __nv_bfloat16* __restrict__ lo, int n) {
    int i = blockIdx.x * 256 + threadIdx.x;
    if (i < n) {
        float x = src[i];
        __nv_bfloat16 h = __float2bfloat16(x);
        hi[i] = h;
        lo[i] = __float2bfloat16(x - __bfloat162float(h));
    }
}

// ---------------- split initial h states ---------------------------------------
__global__ __launch_bounds__(256) void hinit_split_k() {
    int i = blockIdx.x * 256 + threadIdx.x;
    int l = i >> 16;
    int r = i & 65535;
    size_t o = ((size_t)(l * 2)) * (Bb * Hh) + r;
    float x = g_h[o];
    __nv_bfloat16 h = __float2bfloat16(x);
    g_hsp_hi[o] = h;
    g_hsp_lo[o] = __float2bfloat16(x - __bfloat162float(h));
}

// ---------------- transpose + split: src[K][N] -> hi/lo [N][K] ------------------
__global__ __launch_bounds__(256) void tsplit_k(const float* __restrict__ src,
                                                __nv_bfloat16* __restrict__ hi,
                                                __nv_bfloat16* __restrict__ lo,
                                                int K, int N) {
    __shared__ float tile[32][33];
    int k0 = blockIdx.x * 32, n0 = blockIdx.y * 32;
    int tx = threadIdx.x & 31, ty = threadIdx.x >> 5;
#pragma unroll
    for (int j = 0; j < 32; j += 8)
        tile[ty + j][tx] = src[(size_t)(k0 + ty + j) * N + n0 + tx];
    __syncthreads();
#pragma unroll
    for (int j = 0; j < 32; j += 8) {
        float x = tile[tx][ty + j];
        __nv_bfloat16 h = __float2bfloat16(x);
        size_t o = (size_t)(n0 + ty + j) * K + k0 + tx;
        hi[o] = h;
        lo[o] = __float2bfloat16(x - __bfloat162float(h));
    }
}

// ---------------- split-bf16 tensor-core GEMM, fused 3-pass ---------------------
// Per k-chunk: load Ahi/Alo/Bhi/Blo tiles once, run hi*hi + hi*lo + lo*hi.
// Block 128x128, 8 warps, 2-stage pipeline. Dynamic smem 2*4*128*40*2 = 81920 B.
#define FSTG (128 * 40)
__global__ __launch_bounds__(256) void mma_gemm_k(
    const __nv_bfloat16* __restrict__ Ahi, const __nv_bfloat16* __restrict__ Alo,
    const __nv_bfloat16* __restrict__ Bhi, const __nv_bfloat16* __restrict__ Blo,
    const float* __restrict__ bias,
    float* __restrict__ out, int K, int N, int perm, int rowbase)
{
    extern __shared__ __nv_bfloat16 fsm[];

    const int tid  = threadIdx.x;
    const int row0 = rowbase + blockIdx.x * 128;
    const int col0 = blockIdx.y * 128;
    const int wid  = tid >> 5, lane = tid & 31;
    const int wm   = wid >> 2;
    const int wn   = wid & 3;
    const int g    = lane >> 2, tg = lane & 3;

    const int niter = K >> 5;

    float acc[4][4][4];
#pragma unroll
    for (int im = 0; im < 4; im++)
#pragma unroll
        for (int in_ = 0; in_ < 4; in_++)
#pragma unroll
            for (int q = 0; q < 4; q++) acc[im][in_][q] = 0.f;

    const int ca  = tid * 2;
    const int ar0 = ca >> 2,       ao0 = (ca & 3) * 8;
    const int ar1 = (ca + 1) >> 2, ao1 = ((ca + 1) & 3) * 8;

    auto issue = [&](int it, int buf) {
        int k0 = it * 32;
        __nv_bfloat16* base = fsm + buf * 4 * FSTG;
        cp16(base + ar0 * 40 + ao0,            Ahi + (size_t)(row0 + ar0) * K + k0 + ao0);
        cp16(base + ar1 * 40 + ao1,            Ahi + (size_t)(row0 + ar1) * K + k0 + ao1);
        cp16(base + FSTG + ar0 * 40 + ao0,     Alo + (size_t)(row0 + ar0) * K + k0 + ao0);
        cp16(base + FSTG + ar1 * 40 + ao1,     Alo + (size_t)(row0 + ar1) * K + k0 + ao1);
        cp16(base + 2 * FSTG + ar0 * 40 + ao0, Bhi + (size_t)(col0 + ar0) * K + k0 + ao0);
        cp16(base + 2 * FSTG + ar1 * 40 + ao1, Bhi + (size_t)(col0 + ar1) * K + k0 + ao1);
        cp16(base + 3 * FSTG + ar0 * 40 + ao0, Blo + (size_t)(col0 + ar0) * K + k0 + ao0);
        cp16(base + 3 * FSTG + ar1 * 40 + ao1, Blo + (size_t)(col0 + ar1) * K + k0 + ao1);
        cp_commit();
    };

    issue(0, 0);

#pragma unroll 1
    for (int it = 0; it < niter; it++) {
        const int buf = it & 1;
        if (it + 1 < niter) { issue(it + 1, buf ^ 1); cp_wait1(); }
        else                { cp_wait0(); }
        __syncthreads();
        const __nv_bfloat16* Ah = fsm + buf * 4 * FSTG;
        const __nv_bfloat16* Al = Ah + FSTG;
        const __nv_bfloat16* Bh = Ah + 2 * FSTG;
        const __nv_bfloat16* Bl = Ah + 3 * FSTG;

#pragma unroll
        for (int kk = 0; kk < 32; kk += 16) {
            unsigned ah[4][4], bh[4][2], bl[4][2], al[4][4];
#pragma unroll
            for (int im = 0; im < 4; im++) {
                int r = wm * 64 + im * 16;
                ah[im][0] = *(const unsigned*)&Ah[(r + g) * 40 + kk + tg * 2];
                ah[im][1] = *(const unsigned*)&Ah[(r + g + 8) * 40 + kk + tg * 2];
                ah[im][2] = *(const unsigned*)&Ah[(r + g) * 40 + kk + tg * 2 + 8];
                ah[im][3] = *(const unsigned*)&Ah[(r + g + 8) * 40 + kk + tg * 2 + 8];
            }
#pragma unroll
            for (int in_ = 0; in_ < 4; in_++) {
                int nn = wn * 32 + in_ * 8 + g;
                bh[in_][0] = *(const unsigned*)&Bh[nn * 40 + kk + tg * 2];
                bh[in_][1] = *(const unsigned*)&Bh[nn * 40 + kk + tg * 2 + 8];
            }
#pragma unroll
            for (int im = 0; im < 4; im++)
#pragma unroll
                for (int in_ = 0; in_ < 4; in_++)
                    mma16816(acc[im][in_], ah[im][0], ah[im][1], ah[im][2], ah[im][3],
                             bh[in_][0], bh[in_][1]);
#pragma unroll
            for (int in_ = 0; in_ < 4; in_++) {
                int nn = wn * 32 + in_ * 8 + g;
                bl[in_][0] = *(const unsigned*)&Bl[nn * 40 + kk + tg * 2];
                bl[in_][1] = *(const unsigned*)&Bl[nn * 40 + kk + tg * 2 + 8];
            }
#pragma unroll
            for (int im = 0; im < 4; im++)
#pragma unroll
                for (int in_ = 0; in_ < 4; in_++)
                    mma16816(acc[im][in_], ah[im][0], ah[im][1], ah[im][2], ah[im][3],
                             bl[in_][0], bl[in_][1]);
#pragma unroll
            for (int im = 0; im < 4; im++) {
                int r = wm * 64 + im * 16;
                al[im][0] = *(const unsigned*)&Al[(r + g) * 40 + kk + tg * 2];
                al[im][1] = *(const unsigned*)&Al[(r + g + 8) * 40 + kk + tg * 2];
                al[im][2] = *(const unsigned*)&Al[(r + g) * 40 + kk + tg * 2 + 8];
                al[im][3] = *(const unsigned*)&Al[(r + g + 8) * 40 + kk + tg * 2 + 8];
            }
#pragma unroll
            for (int im = 0; im < 4; im++)
#pragma unroll
                for (int in_ = 0; in_ < 4; in_++)
                    mma16816(acc[im][in_], al[im][0], al[im][1], al[im][2], al[im][3],
                             bh[in_][0], bh[in_][1]);
        }
        __syncthreads();
    }

#pragma unroll
    for (int im = 0; im < 4; im++) {
#pragma unroll
        for (int in_ = 0; in_ < 4; in_++) {
            int rr = row0 + wm * 64 + im * 16 + g;
            int cn = col0 + wn * 32 + in_ * 8 + tg * 2;
            float b0v = bias ? bias[cn] : 0.f;
            float b1v = bias ? bias[cn + 1] : 0.f;
#pragma unroll
            for (int half = 0; half < 2; half++) {
                int r = rr + half * 8;
                size_t orow;
                if (perm) {
                    int t = r >> 6, b = r & 63;
                    orow = (size_t)(b * Tt + t);
                } else {
                    orow = (size_t)r;
                }
                float2 v;
                v.x = acc[im][in_][half * 2 + 0] + b0v;
                v.y = acc[im][in_][half * 2 + 1] + b1v;
                *(float2*)(out + orow * N + cn) = v;
            }
        }
    }
}

// ---------------- wavefront LSTM cell: dual wg split-K, fused 3-pass ------------
// wg0 handles x@W (l>0) or half of h@U (l=0); wg1 the other. Per k-chunk:
// 4 tiles (Ahi,Alo,Bhi,Blo) loaded once, 3 mma sweeps. 2-stage per-wg pipeline.
#define WLD 40
#define WSTG (64 * WLD)
__global__ __launch_bounds__(256) void lstm_wave_mma_k(CellArgs args, int s) {
    extern __shared__ __nv_bfloat16 smem[];
    float* Zs = (float*)(smem + 16 * WSTG);       // [64][68]

    const int tid  = threadIdx.x;
    const int wg   = tid >> 7;
    const int wtid = tid & 127;
    __nv_bfloat16* wgbase = smem + wg * 8 * WSTG;

    const int lmin = (s > 63) ? (s - 63) : 0;
    const int l    = lmin + blockIdx.y;
    const int t    = s - l;
    const size_t SH = (size_t)Bb * Hh;
    const int pin  = t & 1, pout = (t + 1) & 1;
    const int j0   = blockIdx.x * 16;

    const __nv_bfloat16* h_hi = g_hsp_hi + (size_t)(l * 2 + pin) * SH;
    const __nv_bfloat16* h_lo = g_hsp_lo + (size_t)(l * 2 + pin) * SH;
    const __nv_bfloat16* Uhi  = g_Usp_hi + (size_t)l * WHH;
    const __nv_bfloat16* Ulo  = g_Usp_lo + (size_t)l * WHH;

    const __nv_bfloat16 *Ah_, *Al_, *Bh_, *Bl_;
    int niter, kbase;
    if (l == 0) {
        Ah_ = h_hi; Al_ = h_lo; Bh_ = Uhi; Bl_ = Ulo;
        niter = 16; kbase = wg * 512;
    } else if (wg == 0) {
        Ah_ = g_hsp_hi + (size_t)((l - 1) * 2 + pout) * SH;
        Al_ = g_hsp_lo + (size_t)((l - 1) * 2 + pout) * SH;
        Bh_ = g_Wsp_hi + (size_t)(l - 1) * WHH;
        Bl_ = g_Wsp_lo + (size_t)(l - 1) * WHH;
        niter = 32; kbase = 0;
    } else {
        Ah_ = h_hi; Al_ = h_lo; Bh_ = Uhi; Bl_ = Ulo;
        niter = 32; kbase = 0;
    }
    const int bid  = wg + 1;

    const int wn   = wtid >> 5;
    const int lane = tid & 31;
    const int g    = lane >> 2, tg = lane & 3;

    // cp coords: tile 64 rows x 32 k; 2 threads/row, 2x16B each
    const int arow = wtid >> 1;
    const int aoff = (wtid & 1) * 16;
    const int bgrow = (arow >> 4) * Hh + j0 + (arow & 15);

    float acc[4][2][4];
#pragma unroll
    for (int im = 0; im < 4; im++)
#pragma unroll
        for (int in_ = 0; in_ < 2; in_++)
#pragma unroll
            for (int q = 0; q < 4; q++) acc[im][in_][q] = 0.f;

    auto issue = [&](int i, int buf) {
        int k0 = kbase + i * 32;
        __nv_bfloat16* base = wgbase + buf * 4 * WSTG;
        cp16(base + arow * WLD + aoff,            Ah_ + (size_t)arow * Hh + k0 + aoff);
        cp16(base + arow * WLD + aoff + 8,        Ah_ + (size_t)arow * Hh + k0 + aoff + 8);
        cp16(base + WSTG + arow * WLD + aoff,     Al_ + (size_t)arow * Hh + k0 + aoff);
        cp16(base + WSTG + arow * WLD + aoff + 8, Al_ + (size_t)arow * Hh + k0 + aoff + 8);
        cp16(base + 2 * WSTG + arow * WLD + aoff,     Bh_ + (size_t)bgrow * Hh + k0 + aoff);
        cp16(base + 2 * WSTG + arow * WLD + aoff + 8, Bh_ + (size_t)bgrow * Hh + k0 + aoff + 8);
        cp16(base + 3 * WSTG + arow * WLD + aoff,     Bl_ + (size_t)bgrow * Hh + k0 + aoff);
        cp16(base + 3 * WSTG + arow * WLD + aoff + 8, Bl_ + (size_t)bgrow * Hh + k0 + aoff + 8);
        cp_commit();
    };

    issue(0, 0);

#pragma unroll 1
    for (int i = 0; i < niter; i++) {
        const int buf = i & 1;
        if (i + 1 < niter) { issue(i + 1, buf ^ 1); cp_wait1(); }
        else               { cp_wait0(); }
        barw(bid);
        const __nv_bfloat16* Ah = wgbase + buf * 4 * WSTG;
        const __nv_bfloat16* Al = Ah + WSTG;
        const __nv_bfloat16* Bh = Ah + 2 * WSTG;
        const __nv_bfloat16* Bl = Ah + 3 * WSTG;

#pragma unroll
        for (int kk = 0; kk < 32; kk += 16) {
            unsigned ah[4][4], bh[2][2], bl[2][2], al[4][4];
#pragma unroll
            for (int im = 0; im < 4; im++) {
                int r = im * 16;
                ah[im][0] = *(const unsigned*)&Ah[(r + g) * WLD + kk + tg * 2];
                ah[im][1] = *(const unsigned*)&Ah[(r + g + 8) * WLD + kk + tg * 2];
                ah[im][2] = *(const unsigned*)&Ah[(r + g) * WLD + kk + tg * 2 + 8];
                ah[im][3] = *(const unsigned*)&Ah[(r + g + 8) * WLD + kk + tg * 2 + 8];
            }
#pragma unroll
            for (int in_ = 0; in_ < 2; in_++) {
                int nn = wn * 16 + in_ * 8 + g;
                bh[in_][0] = *(const unsigned*)&Bh[nn * WLD + kk + tg * 2];
                bh[in_][1] = *(const unsigned*)&Bh[nn * WLD + kk + tg * 2 + 8];
            }
#pragma unroll
            for (int im = 0; im < 4; im++)
#pragma unroll
                for (int in_ = 0; in_ < 2; in_++)
                    mma16816(acc[im][in_], ah[im][0], ah[im][1], ah[im][2], ah[im][3],
                             bh[in_][0], bh[in_][1]);
#pragma unroll
            for (int in_ = 0; in_ < 2; in_++) {
                int nn = wn * 16 + in_ * 8 + g;
                bl[in_][0] = *(const unsigned*)&Bl[nn * WLD + kk + tg * 2];
                bl[in_][1] = *(const unsigned*)&Bl[nn * WLD + kk + tg * 2 + 8];
            }
#pragma unroll
            for (int im = 0; im < 4; im++)
#pragma unroll
                for (int in_ = 0; in_ < 2; in_++)
                    mma16816(acc[im][in_], ah[im][0], ah[im][1], ah[im][2], ah[im][3],
                             bl[in_][0], bl[in_][1]);
#pragma unroll
            for (int im = 0; im < 4; im++) {
                int r = im * 16;
                al[im][0] = *(const unsigned*)&Al[(r + g) * WLD + kk + tg * 2];
                al[im][1] = *(const unsigned*)&Al[(r + g + 8) * WLD + kk + tg * 2];
                al[im][2] = *(const unsigned*)&Al[(r + g) * WLD + kk + tg * 2 + 8];
                al[im][3] = *(const unsigned*)&Al[(r + g + 8) * WLD + kk + tg * 2 + 8];
            }
#pragma unroll
            for (int im = 0; im < 4; im++)
#pragma unroll
                for (int in_ = 0; in_ < 2; in_++)
                    mma16816(acc[im][in_], al[im][0], al[im][1], al[im][2], al[im][3],
                             bh[in_][0], bh[in_][1]);
        }
        barw(bid);
    }

    // combine the two warpgroups' partial sums via Zs
    __syncthreads();
    if (wg == 0) {
#pragma unroll
        for (int im = 0; im < 4; im++)
#pragma unroll
            for (int in_ = 0; in_ < 2; in_++)
#pragma unroll
                for (int q = 0; q < 4; q++) {
                    int r = im * 16 + g + ((q >> 1) << 3);
                    int n = wn * 16 + in_ * 8 + tg * 2 + (q & 1);
                    Zs[r * 68 + n] = acc[im][in_][q];
                }
    }
    __syncthreads();
    if (wg == 1) {
#pragma unroll
        for (int im = 0; im < 4; im++)
#pragma unroll
            for (int in_ = 0; in_ < 2; in_++)
#pragma unroll
                for (int q = 0; q < 4; q++) {
                    int r = im * 16 + g + ((q >> 1) << 3);
                    int n = wn * 16 + in_ * 8 + tg * 2 + (q & 1);
                    Zs[r * 68 + n] += acc[im][in_][q];
                }
    }
    __syncthreads();

    const float* bias = args.b[l];
    float* c = g_c + (size_t)l * SH;
    __nv_bfloat16* ho_hi = g_hsp_hi + (size_t)(l * 2 + pout) * SH;
    __nv_bfloat16* ho_lo = g_hsp_lo + (size_t)(l * 2 + pout) * SH;
    const float* zp = (l == 0) ? (g_zpre + (size_t)t * Bb * 4 * Hh) : nullptr;

#pragma unroll
    for (int q = 0; q < 4; q++) {
        int e  = tid + 256 * q;
        int r  = e >> 4;
        int uu = e & 15;
        int j  = j0 + uu;
        float zi = Zs[r * 68 + uu]      + bias[j];
        float zf = Zs[r * 68 + 16 + uu] + bias[Hh + j];
        float zg = Zs[r * 68 + 32 + uu] + bias[2 * Hh + j];
        float zo = Zs[r * 68 + 48 + uu] + bias[3 * Hh + j];
        if (zp) {
            const float* z = zp + (size_t)r * (4 * Hh);
            zi += z[j]; zf += z[Hh + j]; zg += z[2 * Hh + j]; zo += z[3 * Hh + j];
        }
        float si = 1.f / (1.f + __expf(-zi));
        float sf = 1.f / (1.f + __expf(-zf));
        float so = 1.f / (1.f + __expf(-zo));
        float tg_ = tanhf(zg);
        float cn = sf * c[r * Hh + j] + si * tg_;
        float hn = so * tanhf(cn);
        c[r * Hh + j] = cn;
        __nv_bfloat16 hh = __float2bfloat16(hn);
        float lo = hn - __bfloat162float(hh);
        ho_hi[r * Hh + j] = hh;
        ho_lo[r * Hh + j] = __float2bfloat16(lo);
        if (l == 3) {
            size_t o = ((size_t)t * Bb + r) * Hh + j;
            g_Ahi[o] = hh;
            g_Alo[o] = __float2bfloat16(lo);
        }
    }
}

// ---------------- online softmax, chunked over t --------------------------------
__global__ __launch_bounds__(256) void softmax_k(float* __restrict__ out, int t0) {
    __shared__ float mred[256], sred[256];
    int row = (blockIdx.x >> 4) * Tt + t0 + (blockIdx.x & 15);
    float* p = out + (size_t)row * Vv;
    int tid = threadIdx.x;

    float m = -3.4e38f, sum = 0.f;
    for (int i = tid; i < Vv; i += 256) {
        float x = p[i];
        float mn = fmaxf(m, x);
        sum = sum * __expf(m - mn) + __expf(x - mn);
        m = mn;
    }
    mred[tid] = m; sred[tid] = sum; __syncthreads();
    for (int st = 128; st > 0; st >>= 1) {
        if (tid < st) {
            float m2 = mred[tid + st], s2 = sred[tid + st];
            float mn = fmaxf(mred[tid], m2);
            sred[tid] = sred[tid] * __expf(mred[tid] - mn) + s2 * __expf(m2 - mn);
            mred[tid] = mn;
        }
        __syncthreads();
    }
    float M = mred[0];
    float inv = 1.f / sred[0];
    for (int i = tid; i < Vv; i += 256) p[i] = __expf(p[i] - M) * inv;
}

// ---------------- launch ------------------------------------------------------
extern "C" void kernel_launch(void* const* d_in, const int* in_sizes, int n_in,
                              void* d_out, int out_size) {
    (void)in_sizes; (void)n_in; (void)out_size;
    const int*   tok = (const int*)d_in[0];
    const float* emb = (const float*)d_in[9];
    const float* W[4]; const float* U[4];
    CellArgs args;
    for (int l = 0; l < 4; l++) {
        W[l] = (const float*)d_in[10 + 3 * l];
        U[l] = (const float*)d_in[11 + 3 * l];
        args.b[l] = (const float*)d_in[12 + 3 * l];
    }
    const float* Wfc = (const float*)d_in[22];
    const float* bfc = (const float*)d_in[23];
    float* out = (float*)d_out;

    float *xbuf, *hbuf, *cbuf, *zpre;
    __nv_bfloat16 *Ahi, *Alo, *B1hi, *B1lo, *Bhi, *Blo, *Wsph, *Wspl, *Usph, *Uspl;
    cudaGetSymbolAddress((void**)&xbuf, g_xbuf);
    cudaGetSymbolAddress((void**)&hbuf, g_h);
    cudaGetSymbolAddress((void**)&cbuf, g_c);
    cudaGetSymbolAddress((void**)&zpre, g_zpre);
    cudaGetSymbolAddress((void**)&Ahi,  g_Ahi);
    cudaGetSymbolAddress((void**)&Alo,  g_Alo);
    cudaGetSymbolAddress((void**)&B1hi, g_B1hi);
    cudaGetSymbolAddress((void**)&B1lo, g_B1lo);
    cudaGetSymbolAddress((void**)&Bhi,  g_Bhi);
    cudaGetSymbolAddress((void**)&Blo,  g_Blo);
    cudaGetSymbolAddress((void**)&Wsph, g_Wsp_hi);
    cudaGetSymbolAddress((void**)&Wspl, g_Wsp_lo);
    cudaGetSymbolAddress((void**)&Usph, g_Usp_hi);
    cudaGetSymbolAddress((void**)&Uspl, g_Usp_lo);

    const int wvSmem = 16 * WSTG * 2 + 64 * 68 * 4;   // 81920 + 17408 = 99328 B
    const int fcSmem = 8 * FSTG * 2;                  // 81920 B
    cudaFuncSetAttribute(lstm_wave_mma_k,
                         cudaFuncAttributeMaxDynamicSharedMemorySize, wvSmem);
    cudaFuncSetAttribute(mma_gemm_k,
                         cudaFuncAttributeMaxDynamicSharedMemorySize, fcSmem);

    // side stream + events: created once on the first (non-capture) call
    static cudaStream_t s2 = nullptr;
    static cudaEvent_t evF, evD[4], evJ;
    if (!s2) {
        cudaStreamCreateWithFlags(&s2, cudaStreamNonBlocking);
        cudaEventCreateWithFlags(&evF, cudaEventDisableTiming);
        for (int k = 0; k < 4; k++)
            cudaEventCreateWithFlags(&evD[k], cudaEventDisableTiming);
        cudaEventCreateWithFlags(&evJ, cudaEventDisableTiming);
    }

    const size_t SH = (size_t)Bb * Hh;

    for (int l = 0; l < 4; l++) {
        cudaMemcpyAsync(hbuf + (size_t)(l * 2) * SH, d_in[1 + 2 * l],
                        SH * sizeof(float), cudaMemcpyDeviceToDevice, 0);
        cudaMemcpyAsync(cbuf + (size_t)l * SH, d_in[2 + 2 * l],
                        SH * sizeof(float), cudaMemcpyDeviceToDevice, 0);
    }

    // fork side stream: Wfc transpose+split overlaps everything below
    cudaEventRecord(evF, 0);
    cudaStreamWaitEvent(s2, evF, 0);
    tsplit_k<<<dim3(Hh / 32, Vv / 32), 256, 0, s2>>>(Wfc, Bhi, Blo, Hh, Vv);

    embed_k<<<(Tt * Bb * Ee) / 256, 256>>>(tok, emb);
    hinit_split_k<<<(4 * Bb * Hh) / 256, 256>>>();

    // zpre = x @ W1 on tensor cores
    split_k<<<(4096 * 512) / 256, 256>>>(xbuf, Ahi, Alo, 4096 * 512);
    tsplit_k<<<dim3(Ee / 32, (4 * Hh) / 32), 256>>>(W[0], B1hi, B1lo, Ee, 4 * Hh);
    mma_gemm_k<<<dim3(32, (4 * Hh) / 128), 256, fcSmem>>>(
        Ahi, Alo, B1hi, B1lo, nullptr, zpre, Ee, 4 * Hh, 0, 0);

    // transpose+split recurrent weights
    for (int l = 1; l < 4; l++)
        tsplit_k<<<dim3(Hh / 32, (4 * Hh) / 32), 256>>>(
            W[l], Wsph + (size_t)(l - 1) * WHH, Wspl + (size_t)(l - 1) * WHH,
            Hh, 4 * Hh);
    for (int l = 0; l < 4; l++)
        tsplit_k<<<dim3(Hh / 32, (4 * Hh) / 32), 256>>>(
            U[l], Usph + (size_t)l * WHH, Uspl + (size_t)l * WHH, Hh, 4 * Hh);

    // wavefront over diagonals; FC+softmax chunks overlap on s2
    for (int s = 0; s <= Tt + 3 - 1; s++) {
        int lmin = (s > Tt - 1) ? (s - (Tt - 1)) : 0;
        int lmax = (s < 3) ? s : 3;
        int ny   = lmax - lmin + 1;
        lstm_wave_mma_k<<<dim3(Hh / 16, ny), 256, wvSmem>>>(args, s);
        if (s == 18) cudaEventRecord(evD[0], 0);
        if (s == 34) cudaEventRecord(evD[1], 0);
        if (s == 50) cudaEventRecord(evD[2], 0);
        if (s == 66) cudaEventRecord(evD[3], 0);
    }

    // FC + softmax in 4 row-chunks on the side stream
    for (int k = 0; k < 4; k++) {
        cudaStreamWaitEvent(s2, evD[k], 0);
        mma_gemm_k<<<dim3(8, Vv / 128), 256, fcSmem, s2>>>(
            Ahi, Alo, Bhi, Blo, bfc, out, Hh, Vv, 1, k * 1024);
        softmax_k<<<Bb * 16, 256, 0, s2>>>(out, k * 16);
    }
    cudaEventRecord(evJ, s2);
    cudaStreamWaitEvent(0, evJ, 0);
}

// round 10
// speedup vs baseline: 1.6188x; 1.1059x over previous
#include <cuda_runtime.h>
#include <cuda_bf16.h>

#define Bb 64
#define Tt 64
#define Hh 1024
#define Vv 32000
#define Ee 512
#define WHH (4 * Hh * Hh)

// ---------------- scratch (static device memory; no allocation) ----------------
__device__ float g_xbuf[Tt * Bb * Ee];
__device__ float g_h[8 * Bb * Hh];
__device__ float g_c[4 * Bb * Hh];
__device__ float g_zpre[Tt * Bb * 4 * Hh];
__device__ __nv_bfloat16 g_Ahi[4096 * 1024];
__device__ __nv_bfloat16 g_Alo[4096 * 1024];
__device__ __nv_bfloat16 g_B1hi[4096 * 512];
__device__ __nv_bfloat16 g_B1lo[4096 * 512];
__device__ __nv_bfloat16 g_Bhi[(size_t)Vv * 1024];
__device__ __nv_bfloat16 g_Blo[(size_t)Vv * 1024];
__device__ __nv_bfloat16 g_hsp_hi[8 * Bb * Hh];
__device__ __nv_bfloat16 g_hsp_lo[8 * Bb * Hh];
__device__ __nv_bfloat16 g_Wsp_hi[3 * WHH];
__device__ __nv_bfloat16 g_Wsp_lo[3 * WHH];
__device__ __nv_bfloat16 g_Usp_hi[4 * WHH];
__device__ __nv_bfloat16 g_Usp_lo[4 * WHH];

struct CellArgs {
    const float* b[4];
};

// ---------------- cp.async / ldmatrix / mma helpers -----------------------------
__device__ __forceinline__ void cp16(void* smem_dst, const void* gsrc) {
    unsigned s = (unsigned)__cvta_generic_to_shared(smem_dst);
    asm volatile("cp.async.cg.shared.global [%0], [%1], 16;\n" :: "r"(s), "l"(gsrc));
}
__device__ __forceinline__ void cp_commit() {
    asm volatile("cp.async.commit_group;\n" ::: "memory");
}
__device__ __forceinline__ void cp_wait1() {
    asm volatile("cp.async.wait_group 1;\n" ::: "memory");
}
__device__ __forceinline__ void cp_wait0() {
    asm volatile("cp.async.wait_group 0;\n" ::: "memory");
}
__device__ __forceinline__ void barw(int id) {
    asm volatile("bar.sync %0, 128;" :: "r"(id) : "memory");
}

__device__ __forceinline__ void ldsm_x4(unsigned& r0, unsigned& r1, unsigned& r2,
                                        unsigned& r3, unsigned addr) {
    asm volatile("ldmatrix.sync.aligned.m8n8.x4.shared.b16 {%0,%1,%2,%3}, [%4];"
                 : "=r"(r0), "=r"(r1), "=r"(r2), "=r"(r3) : "r"(addr));
}
__device__ __forceinline__ void ldsm_x2(unsigned& r0, unsigned& r1, unsigned addr) {
    asm volatile("ldmatrix.sync.aligned.m8n8.x2.shared.b16 {%0,%1}, [%2];"
                 : "=r"(r0), "=r"(r1) : "r"(addr));
}

__device__ __forceinline__ void mma16816(float c[4],
                                         unsigned a0, unsigned a1, unsigned a2, unsigned a3,
                                         unsigned b0, unsigned b1) {
    asm volatile(
        "mma.sync.aligned.m16n8k16.row.col.f32.bf16.bf16.f32 "
        "{%0,%1,%2,%3}, {%4,%5,%6,%7}, {%8,%9}, {%0,%1,%2,%3};"
        : "+f"(c[0]), "+f"(c[1]), "+f"(c[2]), "+f"(c[3])
        : "r"(a0), "r"(a1), "r"(a2), "r"(a3), "r"(b0), "r"(b1));
}

// ---------------- embedding lookup ---------------------------------------------
__global__ __launch_bounds__(256) void embed_k(const int* __restrict__ tok,
                                               const float* __restrict__ emb) {
    int idx = blockIdx.x * 256 + threadIdx.x;
    int e  = idx & (Ee - 1);
    int bt = idx >> 9;
    int b  = bt & (Bb - 1);
    int t  = bt >> 6;
    g_xbuf[idx] = emb[(size_t)tok[b * Tt + t] * Ee + e];
}

// ---------------- fp32 -> (hi, lo) bf16 split ----------------------------------
__global__ __launch_bounds__(256) void split_k(const float* __restrict__ src,
                                               __nv_bfloat16* __restrict__ hi,
                                               __nv_bfloat16* __restrict__ lo, int n) {
    int i = blockIdx.x * 256 + threadIdx.x;
    if (i < n) {
        float x = src[i];
        __nv_bfloat16 h = __float2bfloat16(x);
        hi[i] = h;
        lo[i] = __float2bfloat16(x - __bfloat162float(h));
    }
}

// ---------------- split initial h states ---------------------------------------
__global__ __launch_bounds__(256) void hinit_split_k() {
    int i = blockIdx.x * 256 + threadIdx.x;
    int l = i >> 16;
    int r = i & 65535;
    size_t o = ((size_t)(l * 2)) * (Bb * Hh) + r;
    float x = g_h[o];
    __nv_bfloat16 h = __float2bfloat16(x);
    g_hsp_hi[o] = h;
    g_hsp_lo[o] = __float2bfloat16(x - __bfloat162float(h));
}

// ---------------- transpose + split: src[K][N] -> hi/lo [N][K] ------------------
__global__ __launch_bounds__(256) void tsplit_k(const float* __restrict__ src,
                                                __nv_bfloat16* __restrict__ hi,
                                                __nv_bfloat16* __restrict__ lo,
                                                int K, int N) {
    __shared__ float tile[32][33];
    int k0 = blockIdx.x * 32, n0 = blockIdx.y * 32;
    int tx = threadIdx.x & 31, ty = threadIdx.x >> 5;
#pragma unroll
    for (int j = 0; j < 32; j += 8)
        tile[ty + j][tx] = src[(size_t)(k0 + ty + j) * N + n0 + tx];
    __syncthreads();
#pragma unroll
    for (int j = 0; j < 32; j += 8) {
        float x = tile[tx][ty + j];
        __nv_bfloat16 h = __float2bfloat16(x);
        size_t o = (size_t)(n0 + ty + j) * K + k0 + tx;
        hi[o] = h;
        lo[o] = __float2bfloat16(x - __bfloat162float(h));
    }
}

// ---------------- split-bf16 tensor-core GEMM, fused 3-pass + ldmatrix ----------
#define FSTG (128 * 40)
__global__ __launch_bounds__(256) void mma_gemm_k(
    const __nv_bfloat16* __restrict__ Ahi, const __nv_bfloat16* __restrict__ Alo,
    const __nv_bfloat16* __restrict__ Bhi, const __nv_bfloat16* __restrict__ Blo,
    const float* __restrict__ bias,
    float* __restrict__ out, int K, int N, int perm, int rowbase)
{
    extern __shared__ __nv_bfloat16 fsm[];
    const unsigned sbase = (unsigned)__cvta_generic_to_shared(fsm);

    const int tid  = threadIdx.x;
    const int row0 = rowbase + blockIdx.x * 128;
    const int col0 = blockIdx.y * 128;
    const int wid  = tid >> 5, lane = tid & 31;
    const int wm   = wid >> 2;
    const int wn   = wid & 3;
    const int g    = lane >> 2, tg = lane & 3;

    const int la_row = lane & 15;            // ldmatrix A lane offsets
    const int la_k   = (lane >> 4) * 8;
    const int lb_row = lane & 7;             // ldmatrix B lane offsets
    const int lb_k   = ((lane >> 3) & 1) * 8;

    const int niter = K >> 5;

    float acc[4][4][4];
#pragma unroll
    for (int im = 0; im < 4; im++)
#pragma unroll
        for (int in_ = 0; in_ < 4; in_++)
#pragma unroll
            for (int q = 0; q < 4; q++) acc[im][in_][q] = 0.f;

    const int ca  = tid * 2;
    const int ar0 = ca >> 2,       ao0 = (ca & 3) * 8;
    const int ar1 = (ca + 1) >> 2, ao1 = ((ca + 1) & 3) * 8;

    auto issue = [&](int it, int buf) {
        int k0 = it * 32;
        __nv_bfloat16* base = fsm + buf * 4 * FSTG;
        cp16(base + ar0 * 40 + ao0,            Ahi + (size_t)(row0 + ar0) * K + k0 + ao0);
        cp16(base + ar1 * 40 + ao1,            Ahi + (size_t)(row0 + ar1) * K + k0 + ao1);
        cp16(base + FSTG + ar0 * 40 + ao0,     Alo + (size_t)(row0 + ar0) * K + k0 + ao0);
        cp16(base + FSTG + ar1 * 40 + ao1,     Alo + (size_t)(row0 + ar1) * K + k0 + ao1);
        cp16(base + 2 * FSTG + ar0 * 40 + ao0, Bhi + (size_t)(col0 + ar0) * K + k0 + ao0);
        cp16(base + 2 * FSTG + ar1 * 40 + ao1, Bhi + (size_t)(col0 + ar1) * K + k0 + ao1);
        cp16(base + 3 * FSTG + ar0 * 40 + ao0, Blo + (size_t)(col0 + ar0) * K + k0 + ao0);
        cp16(base + 3 * FSTG + ar1 * 40 + ao1, Blo + (size_t)(col0 + ar1) * K + k0 + ao1);
        cp_commit();
    };

    issue(0, 0);

#pragma unroll 1
    for (int it = 0; it < niter; it++) {
        const int buf = it & 1;
        if (it + 1 < niter) { issue(it + 1, buf ^ 1); cp_wait1(); }
        else                { cp_wait0(); }
        __syncthreads();
        const unsigned ahB = sbase + (buf * 4 * FSTG) * 2;
        const unsigned alB = ahB + FSTG * 2;
        const unsigned bhB = ahB + 2 * FSTG * 2;
        const unsigned blB = ahB + 3 * FSTG * 2;

#pragma unroll
        for (int kk = 0; kk < 32; kk += 16) {
            unsigned ah[4][4], bh[4][2], bl[4][2], al[4][4];
#pragma unroll
            for (int im = 0; im < 4; im++)
                ldsm_x4(ah[im][0], ah[im][1], ah[im][2], ah[im][3],
                        ahB + ((wm * 64 + im * 16 + la_row) * 40 + kk + la_k) * 2);
#pragma unroll
            for (int in_ = 0; in_ < 4; in_++)
                ldsm_x2(bh[in_][0], bh[in_][1],
                        bhB + ((wn * 32 + in_ * 8 + lb_row) * 40 + kk + lb_k) * 2);
#pragma unroll
            for (int im = 0; im < 4; im++)
#pragma unroll
                for (int in_ = 0; in_ < 4; in_++)
                    mma16816(acc[im][in_], ah[im][0], ah[im][1], ah[im][2], ah[im][3],
                             bh[in_][0], bh[in_][1]);
#pragma unroll
            for (int in_ = 0; in_ < 4; in_++)
                ldsm_x2(bl[in_][0], bl[in_][1],
                        blB + ((wn * 32 + in_ * 8 + lb_row) * 40 + kk + lb_k) * 2);
#pragma unroll
            for (int im = 0; im < 4; im++)
#pragma unroll
                for (int in_ = 0; in_ < 4; in_++)
                    mma16816(acc[im][in_], ah[im][0], ah[im][1], ah[im][2], ah[im][3],
                             bl[in_][0], bl[in_][1]);
#pragma unroll
            for (int im = 0; im < 4; im++)
                ldsm_x4(al[im][0], al[im][1], al[im][2], al[im][3],
                        alB + ((wm * 64 + im * 16 + la_row) * 40 + kk + la_k) * 2);
#pragma unroll
            for (int im = 0; im < 4; im++)
#pragma unroll
                for (int in_ = 0; in_ < 4; in_++)
                    mma16816(acc[im][in_], al[im][0], al[im][1], al[im][2], al[im][3],
                             bh[in_][0], bh[in_][1]);
        }
        __syncthreads();
    }

#pragma unroll
    for (int im = 0; im < 4; im++) {
#pragma unroll
        for (int in_ = 0; in_ < 4; in_++) {
            int rr = row0 + wm * 64 + im * 16 + g;
            int cn = col0 + wn * 32 + in_ * 8 + tg * 2;
            float b0v = bias ? bias[cn] : 0.f;
            float b1v = bias ? bias[cn + 1] : 0.f;
#pragma unroll
            for (int half = 0; half < 2; half++) {
                int r = rr + half * 8;
                size_t orow;
                if (perm) {
                    int t = r >> 6, b = r & 63;
                    orow = (size_t)(b * Tt + t);
                } else {
                    orow = (size_t)r;
                }
                float2 v;
                v.x = acc[im][in_][half * 2 + 0] + b0v;
                v.y = acc[im][in_][half * 2 + 1] + b1v;
                *(float2*)(out + orow * N + cn) = v;
            }
        }
    }
}

// ---------------- wavefront LSTM cell: dual wg split-K, fused 3-pass + ldmatrix -
#define WLD 40
#define WSTG (64 * WLD)
__global__ __launch_bounds__(256) void lstm_wave_mma_k(CellArgs args, int s) {
    extern __shared__ __nv_bfloat16 smem[];
    float* Zs = (float*)(smem + 16 * WSTG);       // [64][68]
    const unsigned sbase = (unsigned)__cvta_generic_to_shared(smem);

    const int tid  = threadIdx.x;
    const int wg   = tid >> 7;
    const int wtid = tid & 127;
    __nv_bfloat16* wgbase = smem + wg * 8 * WSTG;
    const unsigned wgB = sbase + (wg * 8 * WSTG) * 2;

    const int lmin = (s > 63) ? (s - 63) : 0;
    const int l    = lmin + blockIdx.y;
    const int t    = s - l;
    const size_t SH = (size_t)Bb * Hh;
    const int pin  = t & 1, pout = (t + 1) & 1;
    const int j0   = blockIdx.x * 16;

    const __nv_bfloat16* h_hi = g_hsp_hi + (size_t)(l * 2 + pin) * SH;
    const __nv_bfloat16* h_lo = g_hsp_lo + (size_t)(l * 2 + pin) * SH;
    const __nv_bfloat16* Uhi  = g_Usp_hi + (size_t)l * WHH;
    const __nv_bfloat16* Ulo  = g_Usp_lo + (size_t)l * WHH;

    const __nv_bfloat16 *Ah_, *Al_, *Bh_, *Bl_;
    int niter, kbase;
    if (l == 0) {
        Ah_ = h_hi; Al_ = h_lo; Bh_ = Uhi; Bl_ = Ulo;
        niter = 16; kbase = wg * 512;
    } else if (wg == 0) {
        Ah_ = g_hsp_hi + (size_t)((l - 1) * 2 + pout) * SH;
        Al_ = g_hsp_lo + (size_t)((l - 1) * 2 + pout) * SH;
        Bh_ = g_Wsp_hi + (size_t)(l - 1) * WHH;
        Bl_ = g_Wsp_lo + (size_t)(l - 1) * WHH;
        niter = 32; kbase = 0;
    } else {
        Ah_ = h_hi; Al_ = h_lo; Bh_ = Uhi; Bl_ = Ulo;
        niter = 32; kbase = 0;
    }
    const int bid  = wg + 1;

    const int wn   = wtid >> 5;
    const int lane = tid & 31;
    const int g    = lane >> 2, tg = lane & 3;

    const int la_row = lane & 15;
    const int la_k   = (lane >> 4) * 8;
    const int lb_row = lane & 7;
    const int lb_k   = ((lane >> 3) & 1) * 8;

    // cp coords: tile 64 rows x 32 k; 2 threads/row, 2x16B each
    const int arow = wtid >> 1;
    const int aoff = (wtid & 1) * 16;
    const int bgrow = (arow >> 4) * Hh + j0 + (arow & 15);

    float acc[4][2][4];
#pragma unroll
    for (int im = 0; im < 4; im++)
#pragma unroll
        for (int in_ = 0; in_ < 2; in_++)
#pragma unroll
            for (int q = 0; q < 4; q++) acc[im][in_][q] = 0.f;

    auto issue = [&](int i, int buf) {
        int k0 = kbase + i * 32;
        __nv_bfloat16* base = wgbase + buf * 4 * WSTG;
        cp16(base + arow * WLD + aoff,            Ah_ + (size_t)arow * Hh + k0 + aoff);
        cp16(base + arow * WLD + aoff + 8,        Ah_ + (size_t)arow * Hh + k0 + aoff + 8);
        cp16(base + WSTG + arow * WLD + aoff,     Al_ + (size_t)arow * Hh + k0 + aoff);
        cp16(base + WSTG + arow * WLD + aoff + 8, Al_ + (size_t)arow * Hh + k0 + aoff + 8);
        cp16(base + 2 * WSTG + arow * WLD + aoff,     Bh_ + (size_t)bgrow * Hh + k0 + aoff);
        cp16(base + 2 * WSTG + arow * WLD + aoff + 8, Bh_ + (size_t)bgrow * Hh + k0 + aoff + 8);
        cp16(base + 3 * WSTG + arow * WLD + aoff,     Bl_ + (size_t)bgrow * Hh + k0 + aoff);
        cp16(base + 3 * WSTG + arow * WLD + aoff + 8, Bl_ + (size_t)bgrow * Hh + k0 + aoff + 8);
        cp_commit();
    };

    issue(0, 0);

#pragma unroll 1
    for (int i = 0; i < niter; i++) {
        const int buf = i & 1;
        if (i + 1 < niter) { issue(i + 1, buf ^ 1); cp_wait1(); }
        else               { cp_wait0(); }
        barw(bid);
        const unsigned ahB = wgB + (buf * 4 * WSTG) * 2;
        const unsigned alB = ahB + WSTG * 2;
        const unsigned bhB = ahB + 2 * WSTG * 2;
        const unsigned blB = ahB + 3 * WSTG * 2;

#pragma unroll
        for (int kk = 0; kk < 32; kk += 16) {
            unsigned ah[4][4], bh[2][2], bl[2][2], al[4][4];
#pragma unroll
            for (int im = 0; im < 4; im++)
                ldsm_x4(ah[im][0], ah[im][1], ah[im][2], ah[im][3],
                        ahB + ((im * 16 + la_row) * WLD + kk + la_k) * 2);
#pragma unroll
            for (int in_ = 0; in_ < 2; in_++)
                ldsm_x2(bh[in_][0], bh[in_][1],
                        bhB + ((wn * 16 + in_ * 8 + lb_row) * WLD + kk + lb_k) * 2);
#pragma unroll
            for (int im = 0; im < 4; im++)
#pragma unroll
                for (int in_ = 0; in_ < 2; in_++)
                    mma16816(acc[im][in_], ah[im][0], ah[im][1], ah[im][2], ah[im][3],
                             bh[in_][0], bh[in_][1]);
#pragma unroll
            for (int in_ = 0; in_ < 2; in_++)
                ldsm_x2(bl[in_][0], bl[in_][1],
                        blB + ((wn * 16 + in_ * 8 + lb_row) * WLD + kk + lb_k) * 2);
#pragma unroll
            for (int im = 0; im < 4; im++)
#pragma unroll
                for (int in_ = 0; in_ < 2; in_++)
                    mma16816(acc[im][in_], ah[im][0], ah[im][1], ah[im][2], ah[im][3],
                             bl[in_][0], bl[in_][1]);
#pragma unroll
            for (int im = 0; im < 4; im++)
                ldsm_x4(al[im][0], al[im][1], al[im][2], al[im][3],
                        alB + ((im * 16 + la_row) * WLD + kk + la_k) * 2);
#pragma unroll
            for (int im = 0; im < 4; im++)
#pragma unroll
                for (int in_ = 0; in_ < 2; in_++)
                    mma16816(acc[im][in_], al[im][0], al[im][1], al[im][2], al[im][3],
                             bh[in_][0], bh[in_][1]);
        }
        barw(bid);
    }

    // combine the two warpgroups' partial sums via Zs
    __syncthreads();
    if (wg == 0) {
#pragma unroll
        for (int im = 0; im < 4; im++)
#pragma unroll
            for (int in_ = 0; in_ < 2; in_++)
#pragma unroll
                for (int q = 0; q < 4; q++) {
                    int r = im * 16 + g + ((q >> 1) << 3);
                    int n = wn * 16 + in_ * 8 + tg * 2 + (q & 1);
                    Zs[r * 68 + n] = acc[im][in_][q];
                }
    }
    __syncthreads();
    if (wg == 1) {
#pragma unroll
        for (int im = 0; im < 4; im++)
#pragma unroll
            for (int in_ = 0; in_ < 2; in_++)
#pragma unroll
                for (int q = 0; q < 4; q++) {
                    int r = im * 16 + g + ((q >> 1) << 3);
                    int n = wn * 16 + in_ * 8 + tg * 2 + (q & 1);
                    Zs[r * 68 + n] += acc[im][in_][q];
                }
    }
    __syncthreads();

    const float* bias = args.b[l];
    float* c = g_c + (size_t)l * SH;
    __nv_bfloat16* ho_hi = g_hsp_hi + (size_t)(l * 2 + pout) * SH;
    __nv_bfloat16* ho_lo = g_hsp_lo + (size_t)(l * 2 + pout) * SH;
    const float* zp = (l == 0) ? (g_zpre + (size_t)t * Bb * 4 * Hh) : nullptr;

#pragma unroll
    for (int q = 0; q < 4; q++) {
        int e  = tid + 256 * q;
        int r  = e >> 4;
        int uu = e & 15;
        int j  = j0 + uu;
        float zi = Zs[r * 68 + uu]      + bias[j];
        float zf = Zs[r * 68 + 16 + uu] + bias[Hh + j];
        float zg = Zs[r * 68 + 32 + uu] + bias[2 * Hh + j];
        float zo = Zs[r * 68 + 48 + uu] + bias[3 * Hh + j];
        if (zp) {
            const float* z = zp + (size_t)r * (4 * Hh);
            zi += z[j]; zf += z[Hh + j]; zg += z[2 * Hh + j]; zo += z[3 * Hh + j];
        }
        float si = 1.f / (1.f + __expf(-zi));
        float sf = 1.f / (1.f + __expf(-zf));
        float so = 1.f / (1.f + __expf(-zo));
        float tg_ = tanhf(zg);
        float cn = sf * c[r * Hh + j] + si * tg_;
        float hn = so * tanhf(cn);
        c[r * Hh + j] = cn;
        __nv_bfloat16 hh = __float2bfloat16(hn);
        float lo = hn - __bfloat162float(hh);
        ho_hi[r * Hh + j] = hh;
        ho_lo[r * Hh + j] = __float2bfloat16(lo);
        if (l == 3) {
            size_t o = ((size_t)t * Bb + r) * Hh + j;
            g_Ahi[o] = hh;
            g_Alo[o] = __float2bfloat16(lo);
        }
    }
}

// ---------------- online softmax, chunked over t (8 steps/chunk) ----------------
__global__ __launch_bounds__(256) void softmax_k(float* __restrict__ out, int t0) {
    __shared__ float mred[256], sred[256];
    int row = (blockIdx.x >> 3) * Tt + t0 + (blockIdx.x & 7);
    float* p = out + (size_t)row * Vv;
    int tid = threadIdx.x;

    float m = -3.4e38f, sum = 0.f;
    for (int i = tid; i < Vv; i += 256) {
        float x = p[i];
        float mn = fmaxf(m, x);
        sum = sum * __expf(m - mn) + __expf(x - mn);
        m = mn;
    }
    mred[tid] = m; sred[tid] = sum; __syncthreads();
    for (int st = 128; st > 0; st >>= 1) {
        if (tid < st) {
            float m2 = mred[tid + st], s2 = sred[tid + st];
            float mn = fmaxf(mred[tid], m2);
            sred[tid] = sred[tid] * __expf(mred[tid] - mn) + s2 * __expf(m2 - mn);
            mred[tid] = mn;
        }
        __syncthreads();
    }
    float M = mred[0];
    float inv = 1.f / sred[0];
    for (int i = tid; i < Vv; i += 256) p[i] = __expf(p[i] - M) * inv;
}

// ---------------- launch ------------------------------------------------------
extern "C" void kernel_launch(void* const* d_in, const int* in_sizes, int n_in,
                              void* d_out, int out_size) {
    (void)in_sizes; (void)n_in; (void)out_size;
    const int*   tok = (const int*)d_in[0];
    const float* emb = (const float*)d_in[9];
    const float* W[4]; const float* U[4];
    CellArgs args;
    for (int l = 0; l < 4; l++) {
        W[l] = (const float*)d_in[10 + 3 * l];
        U[l] = (const float*)d_in[11 + 3 * l];
        args.b[l] = (const float*)d_in[12 + 3 * l];
    }
    const float* Wfc = (const float*)d_in[22];
    const float* bfc = (const float*)d_in[23];
    float* out = (float*)d_out;

    float *xbuf, *hbuf, *cbuf, *zpre;
    __nv_bfloat16 *Ahi, *Alo, *B1hi, *B1lo, *Bhi, *Blo, *Wsph, *Wspl, *Usph, *Uspl;
    cudaGetSymbolAddress((void**)&xbuf, g_xbuf);
    cudaGetSymbolAddress((void**)&hbuf, g_h);
    cudaGetSymbolAddress((void**)&cbuf, g_c);
    cudaGetSymbolAddress((void**)&zpre, g_zpre);
    cudaGetSymbolAddress((void**)&Ahi,  g_Ahi);
    cudaGetSymbolAddress((void**)&Alo,  g_Alo);
    cudaGetSymbolAddress((void**)&B1hi, g_B1hi);
    cudaGetSymbolAddress((void**)&B1lo, g_B1lo);
    cudaGetSymbolAddress((void**)&Bhi,  g_Bhi);
    cudaGetSymbolAddress((void**)&Blo,  g_Blo);
    cudaGetSymbolAddress((void**)&Wsph, g_Wsp_hi);
    cudaGetSymbolAddress((void**)&Wspl, g_Wsp_lo);
    cudaGetSymbolAddress((void**)&Usph, g_Usp_hi);
    cudaGetSymbolAddress((void**)&Uspl, g_Usp_lo);

    const int wvSmem = 16 * WSTG * 2 + 64 * 68 * 4;   // 99328 B
    const int fcSmem = 8 * FSTG * 2;                  // 81920 B
    cudaFuncSetAttribute(lstm_wave_mma_k,
                         cudaFuncAttributeMaxDynamicSharedMemorySize, wvSmem);
    cudaFuncSetAttribute(mma_gemm_k,
                         cudaFuncAttributeMaxDynamicSharedMemorySize, fcSmem);

    // side stream + events: created once on the first (non-capture) call
    static cudaStream_t s2 = nullptr;
    static cudaEvent_t evF, evD[8], evJ;
    if (!s2) {
        cudaStreamCreateWithFlags(&s2, cudaStreamNonBlocking);
        cudaEventCreateWithFlags(&evF, cudaEventDisableTiming);
        for (int k = 0; k < 8; k++)
            cudaEventCreateWithFlags(&evD[k], cudaEventDisableTiming);
        cudaEventCreateWithFlags(&evJ, cudaEventDisableTiming);
    }

    const size_t SH = (size_t)Bb * Hh;

    for (int l = 0; l < 4; l++) {
        cudaMemcpyAsync(hbuf + (size_t)(l * 2) * SH, d_in[1 + 2 * l],
                        SH * sizeof(float), cudaMemcpyDeviceToDevice, 0);
        cudaMemcpyAsync(cbuf + (size_t)l * SH, d_in[2 + 2 * l],
                        SH * sizeof(float), cudaMemcpyDeviceToDevice, 0);
    }

    // fork side stream: Wfc transpose+split overlaps everything below
    cudaEventRecord(evF, 0);
    cudaStreamWaitEvent(s2, evF, 0);
    tsplit_k<<<dim3(Hh / 32, Vv / 32), 256, 0, s2>>>(Wfc, Bhi, Blo, Hh, Vv);

    embed_k<<<(Tt * Bb * Ee) / 256, 256>>>(tok, emb);
    hinit_split_k<<<(4 * Bb * Hh) / 256, 256>>>();

    // zpre = x @ W1 on tensor cores
    split_k<<<(4096 * 512) / 256, 256>>>(xbuf, Ahi, Alo, 4096 * 512);
    tsplit_k<<<dim3(Ee / 32, (4 * Hh) / 32), 256>>>(W[0], B1hi, B1lo, Ee, 4 * Hh);
    mma_gemm_k<<<dim3(32, (4 * Hh) / 128), 256, fcSmem>>>(
        Ahi, Alo, B1hi, B1lo, nullptr, zpre, Ee, 4 * Hh, 0, 0);

    // transpose+split recurrent weights
    for (int l = 1; l < 4; l++)
        tsplit_k<<<dim3(Hh / 32, (4 * Hh) / 32), 256>>>(
            W[l], Wsph + (size_t)(l - 1) * WHH, Wspl + (size_t)(l - 1) * WHH,
            Hh, 4 * Hh);
    for (int l = 0; l < 4; l++)
        tsplit_k<<<dim3(Hh / 32, (4 * Hh) / 32), 256>>>(
            U[l], Usph + (size_t)l * WHH, Uspl + (size_t)l * WHH, Hh, 4 * Hh);

    // wavefront over diagonals; FC+softmax chunks overlap on s2
    for (int s = 0; s <= Tt + 3 - 1; s++) {
        int lmin = (s > Tt - 1) ? (s - (Tt - 1)) : 0;
        int lmax = (s < 3) ? s : 3;
        int ny   = lmax - lmin + 1;
        lstm_wave_mma_k<<<dim3(Hh / 16, ny), 256, wvSmem>>>(args, s);
        // h4 rows for t in [8k, 8k+8) complete at diagonal 8k+10
        if (s >= 10 && s <= 66 && ((s - 10) & 7) == 0)
            cudaEventRecord(evD[(s - 10) >> 3], 0);
    }

    // FC + softmax in 8 row-chunks on the side stream
    for (int k = 0; k < 8; k++) {
        cudaStreamWaitEvent(s2, evD[k], 0);
        mma_gemm_k<<<dim3(4, Vv / 128), 256, fcSmem, s2>>>(
            Ahi, Alo, Bhi, Blo, bfc, out, Hh, Vv, 1, k * 512);
        softmax_k<<<Bb * 8, 256, 0, s2>>>(out, k * 8);
    }
    cudaEventRecord(evJ, s2);
    cudaStreamWaitEvent(0, evJ, 0);
}